// round 4
// baseline (speedup 1.0000x reference)
#include <cuda_runtime.h>
#include <cuda_bf16.h>
#include <cstdint>

#define F 128
#define H 4
#define HF 512
#define NRBF 20
#define OUTC 384
#define NODES_MAX 20000
#define EPC 64

// device scratch
__device__ float g_q[NODES_MAX * HF];
__device__ float g_k[NODES_MAX * HF];
__device__ float g_v[NODES_MAX * HF];
__device__ __nv_bfloat16 g_Bhi[OUTC * HF];   // denseW^T hi, [n][k]
__device__ __nv_bfloat16 g_Blo[OUTC * HF];   // denseW^T lo, [n][k]

__device__ __forceinline__ float silu_f(float x) {
    return x * __fdividef(1.f, 1.f + __expf(-x));
}
__device__ __forceinline__ uint32_t smem_u32(const void* p) {
    uint32_t a;
    asm("{ .reg .u64 t; cvta.to.shared.u64 t, %1; cvt.u32.u64 %0, t; }"
        : "=r"(a) : "l"(p));
    return a;
}
__device__ __forceinline__ void ldsm_x4(uint32_t& r0, uint32_t& r1, uint32_t& r2,
                                        uint32_t& r3, uint32_t addr) {
    asm volatile("ldmatrix.sync.aligned.m8n8.x4.shared.b16 {%0,%1,%2,%3}, [%4];"
                 : "=r"(r0), "=r"(r1), "=r"(r2), "=r"(r3) : "r"(addr));
}
__device__ __forceinline__ void mma16816(float* c, const uint32_t* a,
                                         uint32_t b0, uint32_t b1) {
    asm volatile(
        "mma.sync.aligned.m16n8k16.row.col.f32.bf16.bf16.f32 "
        "{%0,%1,%2,%3},{%4,%5,%6,%7},{%8,%9},{%0,%1,%2,%3};"
        : "+f"(c[0]), "+f"(c[1]), "+f"(c[2]), "+f"(c[3])
        : "r"(a[0]), "r"(a[1]), "r"(a[2]), "r"(a[3]), "r"(b0), "r"(b1));
}

// ---------------------------------------------------------------------------
// Kernel 0: transpose + bf16-split denseW [512,384] -> g_Bhi/g_Blo [384][512]
// ---------------------------------------------------------------------------
__global__ void prep_kernel(const float* __restrict__ denseW) {
    int n = blockIdx.x;       // 0..383
    int k = threadIdx.x;      // 0..511
    float wv = denseW[(size_t)k * OUTC + n];
    __nv_bfloat16 hi = __float2bfloat16_rn(wv);
    g_Bhi[n * HF + k] = hi;
    g_Blo[n * HF + k] = __float2bfloat16_rn(wv - __bfloat162float(hi));
}

// ---------------------------------------------------------------------------
// Kernel 1: LayerNorm + QKV GEMM (unchanged, proven)
// ---------------------------------------------------------------------------
__global__ __launch_bounds__(256) void qkv_kernel(
    const float* __restrict__ s_j,
    const float* __restrict__ ln_g, const float* __restrict__ ln_b,
    const float* __restrict__ Wq, const float* __restrict__ bq,
    const float* __restrict__ Wk, const float* __restrict__ bk,
    const float* __restrict__ Wv, const float* __restrict__ bv,
    int n_nodes)
{
    extern __shared__ float sm[];
    float* A = sm;                 // [128][68]
    float* B = sm + 128 * 68;      // [128][128]

    const float* W; const float* bias; float* outp;
    if (blockIdx.z == 0)      { W = Wq; bias = bq; outp = g_q; }
    else if (blockIdx.z == 1) { W = Wk; bias = bk; outp = g_k; }
    else                      { W = Wv; bias = bv; outp = g_v; }

    const int tid  = threadIdx.x;
    const int lane = tid & 31;
    const int warp = tid >> 5;
    const int node0 = blockIdx.x * 64;
    const int colt  = blockIdx.y * 128;

    float4 g4 = *(const float4*)&ln_g[lane * 4];
    float4 b4 = *(const float4*)&ln_b[lane * 4];
    #pragma unroll
    for (int nn = 0; nn < 8; nn++) {
        int nl = warp * 8 + nn;
        int node = node0 + nl;
        float4 x = make_float4(0.f, 0.f, 0.f, 0.f);
        if (node < n_nodes) x = *(const float4*)&s_j[(size_t)node * F + lane * 4];
        float s  = x.x + x.y + x.z + x.w;
        float s2 = x.x * x.x + x.y * x.y + x.z * x.z + x.w * x.w;
        #pragma unroll
        for (int o = 16; o; o >>= 1) {
            s  += __shfl_xor_sync(0xffffffffu, s,  o);
            s2 += __shfl_xor_sync(0xffffffffu, s2, o);
        }
        float mu  = s * (1.f / F);
        float var = s2 * (1.f / F) - mu * mu;
        float rs  = rsqrtf(var + 1e-5f);
        A[(lane * 4 + 0) * 68 + nl] = (x.x - mu) * rs * g4.x + b4.x;
        A[(lane * 4 + 1) * 68 + nl] = (x.y - mu) * rs * g4.y + b4.y;
        A[(lane * 4 + 2) * 68 + nl] = (x.z - mu) * rs * g4.z + b4.z;
        A[(lane * 4 + 3) * 68 + nl] = (x.w - mu) * rs * g4.w + b4.w;
    }

    #pragma unroll
    for (int it = 0; it < 16; it++) {
        int lin = tid + it * 256;
        int row = lin >> 5;
        int c4  = (lin & 31) * 4;
        *(float4*)&B[row * 128 + c4] =
            *(const float4*)&W[(size_t)row * HF + colt + c4];
    }
    __syncthreads();

    const int ng  = tid >> 4;
    const int cgp = tid & 15;
    float acc[4][8];
    #pragma unroll
    for (int i = 0; i < 4; i++)
        #pragma unroll
        for (int j = 0; j < 8; j++) acc[i][j] = 0.f;

    #pragma unroll 4
    for (int k = 0; k < 128; k++) {
        float4 a  = *(float4*)&A[k * 68 + ng * 4];
        float4 b0 = *(float4*)&B[k * 128 + cgp * 8];
        float4 b1 = *(float4*)&B[k * 128 + cgp * 8 + 4];
        float av[4] = {a.x, a.y, a.z, a.w};
        float bv8[8] = {b0.x, b0.y, b0.z, b0.w, b1.x, b1.y, b1.z, b1.w};
        #pragma unroll
        for (int i = 0; i < 4; i++)
            #pragma unroll
            for (int j = 0; j < 8; j++)
                acc[i][j] += av[i] * bv8[j];
    }

    float4 bias0 = *(const float4*)&bias[colt + cgp * 8];
    float4 bias1 = *(const float4*)&bias[colt + cgp * 8 + 4];
    #pragma unroll
    for (int i = 0; i < 4; i++) {
        int node = node0 + ng * 4 + i;
        if (node < n_nodes) {
            float4 o0 = make_float4(acc[i][0] + bias0.x, acc[i][1] + bias0.y,
                                    acc[i][2] + bias0.z, acc[i][3] + bias0.w);
            float4 o1 = make_float4(acc[i][4] + bias1.x, acc[i][5] + bias1.y,
                                    acc[i][6] + bias1.z, acc[i][7] + bias1.w);
            *(float4*)&outp[(size_t)node * HF + colt + cgp * 8]     = o0;
            *(float4*)&outp[(size_t)node * HF + colt + cgp * 8 + 4] = o1;
        }
    }
}

// ---------------------------------------------------------------------------
// Kernel 2: edge kernel. Phases A/B (R1, proven) + phase C via mma.sync bf16x3
// grid = E/64, block 512.
// smem (floats):
//   msg:    [0, 33024)             64x516 fp32
//   scratch:[33024, 50944)         71680 B:
//       phase B: dks [32][512] fp32 (65536 B)
//       phase C: Bhi(30720) Blo(30720) Ahi(5120) Alo(5120)  @ byte 132096
//   rbf:    [50944, 52224)  env: [52224, 52288)  ij(int): [52288, 52416)
// total 209664 B
// ---------------------------------------------------------------------------
#define SMEM_EDGE 209664

__global__ __launch_bounds__(512) void edge_kernel(
    const float* __restrict__ dist, const int* __restrict__ nbrs,
    const float* __restrict__ dkW, const float* __restrict__ dkb,
    const float* __restrict__ dvW, const float* __restrict__ dvb,
    const float* __restrict__ denseb,
    float* __restrict__ out)
{
    extern __shared__ float sm[];
    float* msg = sm;                  // 64*516
    float* dks = sm + 33024;          // phase-B scratch
    float* rbf = sm + 50944;          // 64*20
    float* env = sm + 52224;          // 64
    int*   ij  = (int*)(sm + 52288);  // 128

    char* smc = (char*)sm;
    const uint32_t smb = smem_u32(sm);
    const uint32_t aBhi = smb + 132096u;
    const uint32_t aBlo = aBhi + 30720u;
    const uint32_t aAhi = aBlo + 30720u;
    const uint32_t aAlo = aAhi + 5120u;

    const int tid  = threadIdx.x;
    const int lane = tid & 31;
    const int warp = tid >> 5;
    const int e0 = blockIdx.x * 64;

    // ---- Phase A: edge metadata ----
    if (tid < 128) ij[tid] = nbrs[(size_t)e0 * 2 + tid];
    if (tid < 64) {
        float d = dist[e0 + tid];
        env[tid] = 0.5f * (cospif(d * 0.2f) + 1.f);
    }
    for (int t = tid; t < 64 * NRBF; t += 512) {
        int e = t / NRBF, r = t % NRBF;
        float d = dist[e0 + e];
        float u = (d - (float)r * (5.f / 19.f)) * (19.f / 5.f);
        rbf[t] = __expf(-0.5f * u * u);
    }

    float wk[NRBF], wv[NRBF];
    #pragma unroll
    for (int r = 0; r < NRBF; r++) {
        wk[r] = dkW[r * HF + tid];
        wv[r] = dvW[r * HF + tid];
    }
    const float bk_ = dkb[tid];
    const float bv_ = dvb[tid];
    __syncthreads();

    // ---- Phases B0/B1 ----
    for (int hb = 0; hb < 2; hb++) {
        #pragma unroll 2
        for (int el = 0; el < 32; el++) {
            int e = hb * 32 + el;
            float a = bk_, b = bv_;
            #pragma unroll
            for (int r = 0; r < NRBF; r++) {
                float rb = rbf[e * NRBF + r];
                a += rb * wk[r];
                b += rb * wv[r];
            }
            dks[el * 512 + tid] = silu_f(a);
            msg[e * 516 + tid]  = silu_f(b);
        }
        __syncthreads();

        #pragma unroll
        for (int ee = 0; ee < 2; ee++) {
            int el = warp * 2 + ee;
            int e  = hb * 32 + el;
            int i  = ij[2 * e];
            int j  = ij[2 * e + 1];
            const float* qp = g_q + (size_t)i * HF;
            const float* kp = g_k + (size_t)j * HF;
            const float* vp = g_v + (size_t)j * HF;
            #pragma unroll
            for (int h = 0; h < H; h++) {
                int f4 = h * F + lane * 4;
                float4 q4 = *(const float4*)(qp + f4);
                float4 k4 = *(const float4*)(kp + f4);
                float4 v4 = *(const float4*)(vp + f4);
                float4 dk4 = *(float4*)&dks[el * 512 + f4];
                float4 dv4 = *(float4*)&msg[e * 516 + f4];
                float s = q4.x * dk4.x * k4.x + q4.y * dk4.y * k4.y
                        + q4.z * dk4.z * k4.z + q4.w * dk4.w * k4.w;
                #pragma unroll
                for (int o = 16; o; o >>= 1) s += __shfl_xor_sync(0xffffffffu, s, o);
                float attn = silu_f(s) * env[e];
                float4 m;
                m.x = attn * v4.x * dv4.x;
                m.y = attn * v4.y * dv4.y;
                m.z = attn * v4.z * dv4.z;
                m.w = attn * v4.w * dv4.w;
                *(float4*)&msg[e * 516 + f4] = m;
            }
        }
        __syncthreads();
    }

    // ---- Phase C: out[64][384] = msg @ denseW + b, bf16x3 mma.sync ----
    const int wm = warp >> 2;            // 0..3  (m16 tile)
    const int wn = warp & 3;             // 0..3  (n96 range)
    float acc[12][4];
    #pragma unroll
    for (int f = 0; f < 12; f++)
        #pragma unroll
        for (int q = 0; q < 4; q++) acc[f][q] = 0.f;

    // per-lane ldmatrix address offsets (constant over chunks)
    const uint32_t aoff = (uint32_t)((wm * 16 + (lane & 15)) * 40 + ((lane >> 4) * 8)) * 2u;
    const uint32_t brow = (uint32_t)((lane & 7) + ((lane >> 4) & 1) * 8);
    const uint32_t bcof = (uint32_t)(((lane >> 3) & 1) * 8);

    // A-conversion indices
    const int ce = tid >> 3;             // edge 0..63
    const int ck = (tid & 7) * 4;        // k 0..28

    for (int c = 0; c < 16; c++) {
        __syncthreads();   // prior chunk's ldmatrix reads done; msg ready (c==0)

        // convert A chunk: msg[:, c*32 .. +32) -> Ahi/Alo bf16 [64][40]
        {
            float4 m = *(float4*)&msg[ce * 516 + c * 32 + ck];
            __nv_bfloat162 h01 = __float22bfloat162_rn(make_float2(m.x, m.y));
            __nv_bfloat162 h23 = __float22bfloat162_rn(make_float2(m.z, m.w));
            float2 l01 = make_float2(m.x - __bfloat162float(h01.x),
                                     m.y - __bfloat162float(h01.y));
            float2 l23 = make_float2(m.z - __bfloat162float(h23.x),
                                     m.w - __bfloat162float(h23.y));
            __nv_bfloat162 lo01 = __float22bfloat162_rn(l01);
            __nv_bfloat162 lo23 = __float22bfloat162_rn(l23);
            uint32_t off = (uint32_t)(ce * 40 + ck) * 2u;
            uint2 hv, lv;
            hv.x = *(uint32_t*)&h01;  hv.y = *(uint32_t*)&h23;
            lv.x = *(uint32_t*)&lo01; lv.y = *(uint32_t*)&lo23;
            *(uint2*)(smc + (aAhi - smb) + off) = hv;
            *(uint2*)(smc + (aAlo - smb) + off) = lv;
        }

        // load B chunk: g_Bhi/g_Blo[:, c*32 .. +32) -> [384][40] bf16
        #pragma unroll
        for (int it = 0; it < 3; it++) {
            int s = it * 512 + tid;
            int n = s >> 2, q = s & 3;
            size_t go = ((size_t)n * HF + c * 32 + q * 8) * 2;
            uint32_t so = (uint32_t)(n * 40 + q * 8) * 2u;
            *(float4*)(smc + (aBhi - smb) + so) = *(const float4*)((const char*)g_Bhi + go);
            *(float4*)(smc + (aBlo - smb) + so) = *(const float4*)((const char*)g_Blo + go);
        }
        __syncthreads();

        // mma: 2 k16 steps
        #pragma unroll
        for (int s = 0; s < 2; s++) {
            uint32_t ah[4], al[4];
            ldsm_x4(ah[0], ah[1], ah[2], ah[3], aAhi + aoff + s * 32);
            ldsm_x4(al[0], al[1], al[2], al[3], aAlo + aoff + s * 32);
            #pragma unroll
            for (int f2 = 0; f2 < 6; f2++) {
                uint32_t n0 = (uint32_t)(wn * 96 + f2 * 16);
                uint32_t boff = ((n0 + brow) * 40 + bcof) * 2u + s * 32;
                uint32_t bh[4], bl[4];
                ldsm_x4(bh[0], bh[1], bh[2], bh[3], aBhi + boff);
                ldsm_x4(bl[0], bl[1], bl[2], bl[3], aBlo + boff);
                mma16816(acc[2 * f2],     ah, bh[0], bh[1]);
                mma16816(acc[2 * f2 + 1], ah, bh[2], bh[3]);
                mma16816(acc[2 * f2],     ah, bl[0], bl[1]);
                mma16816(acc[2 * f2 + 1], ah, bl[2], bl[3]);
                mma16816(acc[2 * f2],     al, bh[0], bh[1]);
                mma16816(acc[2 * f2 + 1], al, bh[2], bh[3]);
            }
        }
    }

    // ---- epilogue ----
    {
        const int g   = lane >> 2;
        const int tig = lane & 3;
        const size_t r0 = (size_t)(e0 + wm * 16 + g) * OUTC;
        const size_t r1 = r0 + 8 * OUTC;
        #pragma unroll
        for (int f = 0; f < 12; f++) {
            int col = wn * 96 + f * 8 + tig * 2;
            float2 b2 = *(const float2*)&denseb[col];
            float2 o0 = make_float2(acc[f][0] + b2.x, acc[f][1] + b2.y);
            float2 o1 = make_float2(acc[f][2] + b2.x, acc[f][3] + b2.y);
            *(float2*)&out[r0 + col] = o0;
            *(float2*)&out[r1 + col] = o1;
        }
    }
}

// ---------------------------------------------------------------------------
extern "C" void kernel_launch(void* const* d_in, const int* in_sizes, int n_in,
                              void* d_out, int out_size)
{
    const float* s_j    = (const float*)d_in[0];
    const float* dist   = (const float*)d_in[1];
    const int*   nbrs   = (const int*)  d_in[2];
    const float* ln_g   = (const float*)d_in[3];
    const float* ln_b   = (const float*)d_in[4];
    const float* Wq     = (const float*)d_in[5];
    const float* bq     = (const float*)d_in[6];
    const float* Wk     = (const float*)d_in[7];
    const float* bk     = (const float*)d_in[8];
    const float* Wv     = (const float*)d_in[9];
    const float* bv     = (const float*)d_in[10];
    const float* dkW    = (const float*)d_in[11];
    const float* dkb    = (const float*)d_in[12];
    const float* dvW    = (const float*)d_in[13];
    const float* dvb    = (const float*)d_in[14];
    const float* denseW = (const float*)d_in[15];
    const float* denseb = (const float*)d_in[16];
    float* out = (float*)d_out;

    int n_nodes = in_sizes[0] / F;    // 20000
    int n_edges = in_sizes[1];        // 160000

    const int smem_q = (128 * 68 + 128 * 128) * 4;

    cudaFuncSetAttribute(qkv_kernel,  cudaFuncAttributeMaxDynamicSharedMemorySize, smem_q);
    cudaFuncSetAttribute(edge_kernel, cudaFuncAttributeMaxDynamicSharedMemorySize, SMEM_EDGE);

    prep_kernel<<<OUTC, HF>>>(denseW);

    dim3 gq((n_nodes + 63) / 64, 4, 3);
    qkv_kernel<<<gq, 256, smem_q>>>(s_j, ln_g, ln_b, Wq, bq, Wk, bk, Wv, bv, n_nodes);

    edge_kernel<<<n_edges / EPC, 512, SMEM_EDGE>>>(
        dist, nbrs, dkW, dkb, dvW, dvb, denseb, out);
}

// round 5
// speedup vs baseline: 1.0930x; 1.0930x over previous
#include <cuda_runtime.h>
#include <cuda_bf16.h>
#include <cstdint>

#define F 128
#define H 4
#define HF 512
#define NRBF 20
#define OUTC 384
#define NODES_MAX 20000
#define EPC 64

__device__ float g_q[NODES_MAX * HF];
__device__ float g_k[NODES_MAX * HF];
__device__ float g_v[NODES_MAX * HF];
__device__ __nv_bfloat16 g_Bhi[OUTC * HF];   // denseW^T hi, [n][k]
__device__ __nv_bfloat16 g_Blo[OUTC * HF];   // denseW^T lo, [n][k]

__device__ __forceinline__ float silu_f(float x) {
    return x * __fdividef(1.f, 1.f + __expf(-x));
}
__device__ __forceinline__ uint32_t smem_u32(const void* p) {
    uint32_t a;
    asm("{ .reg .u64 t; cvta.to.shared.u64 t, %1; cvt.u32.u64 %0, t; }"
        : "=r"(a) : "l"(p));
    return a;
}
__device__ __forceinline__ void ldsm_x4(uint32_t& r0, uint32_t& r1, uint32_t& r2,
                                        uint32_t& r3, uint32_t addr) {
    asm volatile("ldmatrix.sync.aligned.m8n8.x4.shared.b16 {%0,%1,%2,%3}, [%4];"
                 : "=r"(r0), "=r"(r1), "=r"(r2), "=r"(r3) : "r"(addr));
}
__device__ __forceinline__ void mma16816(float* c, const uint32_t* a,
                                         uint32_t b0, uint32_t b1) {
    asm volatile(
        "mma.sync.aligned.m16n8k16.row.col.f32.bf16.bf16.f32 "
        "{%0,%1,%2,%3},{%4,%5,%6,%7},{%8,%9},{%0,%1,%2,%3};"
        : "+f"(c[0]), "+f"(c[1]), "+f"(c[2]), "+f"(c[3])
        : "r"(a[0]), "r"(a[1]), "r"(a[2]), "r"(a[3]), "r"(b0), "r"(b1));
}
__device__ __forceinline__ void split_bf16(float x, __nv_bfloat16& hi, __nv_bfloat16& lo) {
    hi = __float2bfloat16_rn(x);
    lo = __float2bfloat16_rn(x - __bfloat162float(hi));
}

// ---------------------------------------------------------------------------
// Kernel 1: LN + QKV via bf16x3 mma, plus (z==3) denseW prep blocks.
// grid (157, 4, 4), block 512.
// z<3: 128 nodes (x) x 128 cols (y) of matrix z.
// smem: Ahi[128][136] Alo Bhi[128][136] Blo  (bf16) = 139264 B
// ---------------------------------------------------------------------------
#define QS_AH 0u
#define QS_AL 34816u
#define QS_BH 69632u
#define QS_BL 104448u
#define SMEM_QKV 139264

__global__ __launch_bounds__(512) void qkv_mma_kernel(
    const float* __restrict__ s_j,
    const float* __restrict__ ln_g, const float* __restrict__ ln_b,
    const float* __restrict__ Wq, const float* __restrict__ bq,
    const float* __restrict__ Wk, const float* __restrict__ bk,
    const float* __restrict__ Wv, const float* __restrict__ bv,
    const float* __restrict__ denseW, int n_nodes)
{
    const int t = threadIdx.x, lane = t & 31, w = t >> 5;

    if (blockIdx.z == 3) {   // denseW prep: b = n row of B^T
        int b = blockIdx.y * 157 + blockIdx.x;
        if (b < OUTC) {
            float wv = denseW[(size_t)t * OUTC + b];
            __nv_bfloat16 hi, lo; split_bf16(wv, hi, lo);
            g_Bhi[b * HF + t] = hi;
            g_Blo[b * HF + t] = lo;
        }
        return;
    }

    extern __shared__ char smc[];
    const uint32_t smb = smem_u32(smc);
    const int m = blockIdx.z;
    const int node0 = blockIdx.x * 128;
    const int ncb = blockIdx.y * 128;
    const float* W = (m == 0) ? Wq : (m == 1) ? Wk : Wv;

    // --- LayerNorm -> A hi/lo tiles [128][136] ---
    float4 g4 = *(const float4*)&ln_g[lane * 4];
    float4 b4 = *(const float4*)&ln_b[lane * 4];
    #pragma unroll
    for (int nn = 0; nn < 8; nn++) {
        int nl = w * 8 + nn;
        int node = node0 + nl;
        float4 x = make_float4(0.f, 0.f, 0.f, 0.f);
        if (node < n_nodes) x = *(const float4*)&s_j[(size_t)node * F + lane * 4];
        float s  = x.x + x.y + x.z + x.w;
        float s2 = x.x * x.x + x.y * x.y + x.z * x.z + x.w * x.w;
        #pragma unroll
        for (int o = 16; o; o >>= 1) {
            s  += __shfl_xor_sync(0xffffffffu, s,  o);
            s2 += __shfl_xor_sync(0xffffffffu, s2, o);
        }
        float mu = s * (1.f / F);
        float var = s2 * (1.f / F) - mu * mu;
        float rs = rsqrtf(var + 1e-5f);
        float y[4] = {(x.x - mu) * rs * g4.x + b4.x, (x.y - mu) * rs * g4.y + b4.y,
                      (x.z - mu) * rs * g4.z + b4.z, (x.w - mu) * rs * g4.w + b4.w};
        __nv_bfloat16 h0, l0, h1, l1, h2, l2, h3, l3;
        split_bf16(y[0], h0, l0); split_bf16(y[1], h1, l1);
        split_bf16(y[2], h2, l2); split_bf16(y[3], h3, l3);
        uint32_t off = (uint32_t)(nl * 136 + lane * 4) * 2u;
        __nv_bfloat162 hp0 = __halves2bfloat162(h0, h1), hp1 = __halves2bfloat162(h2, h3);
        __nv_bfloat162 lp0 = __halves2bfloat162(l0, l1), lp1 = __halves2bfloat162(l2, l3);
        uint2 hv, lv;
        hv.x = *(uint32_t*)&hp0; hv.y = *(uint32_t*)&hp1;
        lv.x = *(uint32_t*)&lp0; lv.y = *(uint32_t*)&lp1;
        *(uint2*)(smc + QS_AH + off) = hv;
        *(uint2*)(smc + QS_AL + off) = lv;
    }

    // --- B tile: W[k][ncb..+128] fp32 -> hi/lo smem [n][k] stride 136 ---
    #pragma unroll
    for (int it = 0; it < 8; it++) {
        int s = it * 512 + t;            // 4096 float4 slots
        int k = s >> 5, n4 = (s & 31) * 4;
        float4 wv = *(const float4*)&W[(size_t)k * HF + ncb + n4];
        float vv[4] = {wv.x, wv.y, wv.z, wv.w};
        #pragma unroll
        for (int i = 0; i < 4; i++) {
            __nv_bfloat16 hi, lo; split_bf16(vv[i], hi, lo);
            uint32_t off = (uint32_t)((n4 + i) * 136 + k) * 2u;
            *(__nv_bfloat16*)(smc + QS_BH + off) = hi;
            *(__nv_bfloat16*)(smc + QS_BL + off) = lo;
        }
    }
    __syncthreads();

    // --- mma: warp wm3 = w>>1 (m16), wn3 = w&1 (n64) ---
    const int wm3 = w >> 1, wn3 = w & 1;
    float acc[8][4];
    #pragma unroll
    for (int f = 0; f < 8; f++)
        #pragma unroll
        for (int q = 0; q < 4; q++) acc[f][q] = 0.f;

    const uint32_t aoff = (uint32_t)((wm3 * 16 + (lane & 15)) * 136 + (lane >> 4) * 8) * 2u;
    const uint32_t brow = (uint32_t)((lane & 7) + ((lane >> 4) & 1) * 8);
    const uint32_t bcof = (uint32_t)(((lane >> 3) & 1) * 8);

    #pragma unroll
    for (int s = 0; s < 8; s++) {
        uint32_t ah[4], al[4];
        ldsm_x4(ah[0], ah[1], ah[2], ah[3], smb + QS_AH + aoff + s * 32);
        ldsm_x4(al[0], al[1], al[2], al[3], smb + QS_AL + aoff + s * 32);
        #pragma unroll
        for (int f = 0; f < 4; f++) {
            uint32_t n0 = (uint32_t)(wn3 * 64 + f * 16);
            uint32_t boff = ((n0 + brow) * 136 + bcof) * 2u + s * 32;
            uint32_t bh[4], bl[4];
            ldsm_x4(bh[0], bh[1], bh[2], bh[3], smb + QS_BH + boff);
            ldsm_x4(bl[0], bl[1], bl[2], bl[3], smb + QS_BL + boff);
            mma16816(acc[2 * f],     ah, bh[0], bh[1]);
            mma16816(acc[2 * f + 1], ah, bh[2], bh[3]);
            mma16816(acc[2 * f],     ah, bl[0], bl[1]);
            mma16816(acc[2 * f + 1], ah, bl[2], bl[3]);
            mma16816(acc[2 * f],     al, bh[0], bh[1]);
            mma16816(acc[2 * f + 1], al, bh[2], bh[3]);
        }
    }

    // --- epilogue ---
    float* outp = (m == 0) ? g_q : (m == 1) ? g_k : g_v;
    const float* bias = (m == 0) ? bq : (m == 1) ? bk : bv;
    const int g = lane >> 2, tig = lane & 3;
    int na = node0 + wm3 * 16 + g;
    int nb = na + 8;
    #pragma unroll
    for (int f = 0; f < 8; f++) {
        int col = ncb + wn3 * 64 + f * 8 + tig * 2;
        float2 b2 = *(const float2*)&bias[col];
        if (na < n_nodes)
            *(float2*)&outp[(size_t)na * HF + col] =
                make_float2(acc[f][0] + b2.x, acc[f][1] + b2.y);
        if (nb < n_nodes)
            *(float2*)&outp[(size_t)nb * HF + col] =
                make_float2(acc[f][2] + b2.x, acc[f][3] + b2.y);
    }
}

// ---------------------------------------------------------------------------
// Kernel 2: edge kernel (R3-proven, B0 uses float4 rbf loads).
// ---------------------------------------------------------------------------
#define SMEM_EDGE 209664

__global__ __launch_bounds__(512) void edge_kernel(
    const float* __restrict__ dist, const int* __restrict__ nbrs,
    const float* __restrict__ dkW, const float* __restrict__ dkb,
    const float* __restrict__ dvW, const float* __restrict__ dvb,
    const float* __restrict__ denseb,
    float* __restrict__ out)
{
    extern __shared__ float sm[];
    float* msg = sm;                  // 64*516
    float* dks = sm + 33024;
    float* rbf = sm + 50944;          // 64*20
    float* env = sm + 52224;
    int*   ij  = (int*)(sm + 52288);

    char* smc = (char*)sm;
    const uint32_t smb = smem_u32(sm);
    const uint32_t aBhi = smb + 132096u;
    const uint32_t aBlo = aBhi + 30720u;
    const uint32_t aAhi = aBlo + 30720u;
    const uint32_t aAlo = aAhi + 5120u;

    const int tid  = threadIdx.x;
    const int lane = tid & 31;
    const int warp = tid >> 5;
    const int e0 = blockIdx.x * 64;

    if (tid < 128) ij[tid] = nbrs[(size_t)e0 * 2 + tid];
    if (tid < 64) {
        float d = dist[e0 + tid];
        env[tid] = 0.5f * (cospif(d * 0.2f) + 1.f);
    }
    for (int t = tid; t < 64 * NRBF; t += 512) {
        int e = t / NRBF, r = t % NRBF;
        float d = dist[e0 + e];
        float u = (d - (float)r * (5.f / 19.f)) * (19.f / 5.f);
        rbf[t] = __expf(-0.5f * u * u);
    }

    float wk[NRBF], wv[NRBF];
    #pragma unroll
    for (int r = 0; r < NRBF; r++) {
        wk[r] = dkW[r * HF + tid];
        wv[r] = dvW[r * HF + tid];
    }
    const float bk_ = dkb[tid];
    const float bv_ = dvb[tid];
    __syncthreads();

    for (int hb = 0; hb < 2; hb++) {
        #pragma unroll 2
        for (int el = 0; el < 32; el++) {
            int e = hb * 32 + el;
            float a = bk_, b = bv_;
            #pragma unroll
            for (int r = 0; r < NRBF; r += 4) {
                float4 rb = *(float4*)&rbf[e * NRBF + r];
                a += rb.x * wk[r] + rb.y * wk[r + 1] + rb.z * wk[r + 2] + rb.w * wk[r + 3];
                b += rb.x * wv[r] + rb.y * wv[r + 1] + rb.z * wv[r + 2] + rb.w * wv[r + 3];
            }
            dks[el * 512 + tid] = silu_f(a);
            msg[e * 516 + tid]  = silu_f(b);
        }
        __syncthreads();

        #pragma unroll
        for (int ee = 0; ee < 2; ee++) {
            int el = warp * 2 + ee;
            int e  = hb * 32 + el;
            int i  = ij[2 * e];
            int j  = ij[2 * e + 1];
            const float* qp = g_q + (size_t)i * HF;
            const float* kp = g_k + (size_t)j * HF;
            const float* vp = g_v + (size_t)j * HF;
            #pragma unroll
            for (int h = 0; h < H; h++) {
                int f4 = h * F + lane * 4;
                float4 q4 = *(const float4*)(qp + f4);
                float4 k4 = *(const float4*)(kp + f4);
                float4 v4 = *(const float4*)(vp + f4);
                float4 dk4 = *(float4*)&dks[el * 512 + f4];
                float4 dv4 = *(float4*)&msg[e * 516 + f4];
                float s = q4.x * dk4.x * k4.x + q4.y * dk4.y * k4.y
                        + q4.z * dk4.z * k4.z + q4.w * dk4.w * k4.w;
                #pragma unroll
                for (int o = 16; o; o >>= 1) s += __shfl_xor_sync(0xffffffffu, s, o);
                float attn = silu_f(s) * env[e];
                float4 mv;
                mv.x = attn * v4.x * dv4.x;
                mv.y = attn * v4.y * dv4.y;
                mv.z = attn * v4.z * dv4.z;
                mv.w = attn * v4.w * dv4.w;
                *(float4*)&msg[e * 516 + f4] = mv;
            }
        }
        __syncthreads();
    }

    // ---- Phase C: bf16x3 mma (unchanged from R3) ----
    const int wm = warp >> 2;
    const int wn = warp & 3;
    float acc[12][4];
    #pragma unroll
    for (int f = 0; f < 12; f++)
        #pragma unroll
        for (int q = 0; q < 4; q++) acc[f][q] = 0.f;

    const uint32_t aoff = (uint32_t)((wm * 16 + (lane & 15)) * 40 + ((lane >> 4) * 8)) * 2u;
    const uint32_t brow = (uint32_t)((lane & 7) + ((lane >> 4) & 1) * 8);
    const uint32_t bcof = (uint32_t)(((lane >> 3) & 1) * 8);
    const int ce = tid >> 3;
    const int ck = (tid & 7) * 4;

    for (int c = 0; c < 16; c++) {
        __syncthreads();
        {
            float4 mv = *(float4*)&msg[ce * 516 + c * 32 + ck];
            __nv_bfloat16 h0, l0, h1, l1, h2, l2, h3, l3;
            split_bf16(mv.x, h0, l0); split_bf16(mv.y, h1, l1);
            split_bf16(mv.z, h2, l2); split_bf16(mv.w, h3, l3);
            __nv_bfloat162 hp0 = __halves2bfloat162(h0, h1), hp1 = __halves2bfloat162(h2, h3);
            __nv_bfloat162 lp0 = __halves2bfloat162(l0, l1), lp1 = __halves2bfloat162(l2, l3);
            uint32_t off = (uint32_t)(ce * 40 + ck) * 2u;
            uint2 hv, lv;
            hv.x = *(uint32_t*)&hp0; hv.y = *(uint32_t*)&hp1;
            lv.x = *(uint32_t*)&lp0; lv.y = *(uint32_t*)&lp1;
            *(uint2*)(smc + (aAhi - smb) + off) = hv;
            *(uint2*)(smc + (aAlo - smb) + off) = lv;
        }
        #pragma unroll
        for (int it = 0; it < 3; it++) {
            int s = it * 512 + tid;
            int n = s >> 2, q = s & 3;
            size_t go = ((size_t)n * HF + c * 32 + q * 8) * 2;
            uint32_t so = (uint32_t)(n * 40 + q * 8) * 2u;
            *(float4*)(smc + (aBhi - smb) + so) = *(const float4*)((const char*)g_Bhi + go);
            *(float4*)(smc + (aBlo - smb) + so) = *(const float4*)((const char*)g_Blo + go);
        }
        __syncthreads();

        #pragma unroll
        for (int s = 0; s < 2; s++) {
            uint32_t ah[4], al[4];
            ldsm_x4(ah[0], ah[1], ah[2], ah[3], aAhi + aoff + s * 32);
            ldsm_x4(al[0], al[1], al[2], al[3], aAlo + aoff + s * 32);
            #pragma unroll
            for (int f2 = 0; f2 < 6; f2++) {
                uint32_t n0 = (uint32_t)(wn * 96 + f2 * 16);
                uint32_t boff = ((n0 + brow) * 40 + bcof) * 2u + s * 32;
                uint32_t bh[4], bl[4];
                ldsm_x4(bh[0], bh[1], bh[2], bh[3], aBhi + boff);
                ldsm_x4(bl[0], bl[1], bl[2], bl[3], aBlo + boff);
                mma16816(acc[2 * f2],     ah, bh[0], bh[1]);
                mma16816(acc[2 * f2 + 1], ah, bh[2], bh[3]);
                mma16816(acc[2 * f2],     ah, bl[0], bl[1]);
                mma16816(acc[2 * f2 + 1], ah, bl[2], bl[3]);
                mma16816(acc[2 * f2],     al, bh[0], bh[1]);
                mma16816(acc[2 * f2 + 1], al, bh[2], bh[3]);
            }
        }
    }

    {
        const int g   = lane >> 2;
        const int tig = lane & 3;
        const size_t r0 = (size_t)(e0 + wm * 16 + g) * OUTC;
        const size_t r1 = r0 + 8 * OUTC;
        #pragma unroll
        for (int f = 0; f < 12; f++) {
            int col = wn * 96 + f * 8 + tig * 2;
            float2 b2 = *(const float2*)&denseb[col];
            *(float2*)&out[r0 + col] = make_float2(acc[f][0] + b2.x, acc[f][1] + b2.y);
            *(float2*)&out[r1 + col] = make_float2(acc[f][2] + b2.x, acc[f][3] + b2.y);
        }
    }
}

// ---------------------------------------------------------------------------
extern "C" void kernel_launch(void* const* d_in, const int* in_sizes, int n_in,
                              void* d_out, int out_size)
{
    const float* s_j    = (const float*)d_in[0];
    const float* dist   = (const float*)d_in[1];
    const int*   nbrs   = (const int*)  d_in[2];
    const float* ln_g   = (const float*)d_in[3];
    const float* ln_b   = (const float*)d_in[4];
    const float* Wq     = (const float*)d_in[5];
    const float* bq     = (const float*)d_in[6];
    const float* Wk     = (const float*)d_in[7];
    const float* bk     = (const float*)d_in[8];
    const float* Wv     = (const float*)d_in[9];
    const float* bv     = (const float*)d_in[10];
    const float* dkW    = (const float*)d_in[11];
    const float* dkb    = (const float*)d_in[12];
    const float* dvW    = (const float*)d_in[13];
    const float* dvb    = (const float*)d_in[14];
    const float* denseW = (const float*)d_in[15];
    const float* denseb = (const float*)d_in[16];
    float* out = (float*)d_out;

    int n_nodes = in_sizes[0] / F;    // 20000
    int n_edges = in_sizes[1];        // 160000

    cudaFuncSetAttribute(qkv_mma_kernel, cudaFuncAttributeMaxDynamicSharedMemorySize, SMEM_QKV);
    cudaFuncSetAttribute(edge_kernel,    cudaFuncAttributeMaxDynamicSharedMemorySize, SMEM_EDGE);

    dim3 gq((n_nodes + 127) / 128, 4, 4);
    qkv_mma_kernel<<<gq, 512, SMEM_QKV>>>(s_j, ln_g, ln_b, Wq, bq, Wk, bk, Wv, bv,
                                          denseW, n_nodes);

    edge_kernel<<<n_edges / EPC, 512, SMEM_EDGE>>>(
        dist, nbrs, dkW, dkb, dvW, dvb, denseb, out);
}

// round 6
// speedup vs baseline: 1.2642x; 1.1566x over previous
#include <cuda_runtime.h>
#include <cuda_bf16.h>
#include <cstdint>

#define F 128
#define H 4
#define HF 512
#define NRBF 20
#define OUTC 384
#define NODES_MAX 20000
#define NEDGE 160000

__device__ float g_q[NODES_MAX * HF];
__device__ float g_k[NODES_MAX * HF];
__device__ float g_v[NODES_MAX * HF];
__device__ __nv_bfloat16 g_Bhi[OUTC * HF];     // denseW^T hi, [n][k]
__device__ __nv_bfloat16 g_Blo[OUTC * HF];     // denseW^T lo, [n][k]
__device__ __nv_bfloat16 g_msgh[NEDGE * HF];   // msg hi, [e][k]
__device__ __nv_bfloat16 g_msgl[NEDGE * HF];   // msg lo, [e][k]

__device__ __forceinline__ float silu_f(float x) {
    return x * __fdividef(1.f, 1.f + __expf(-x));
}
__device__ __forceinline__ uint32_t smem_u32(const void* p) {
    uint32_t a;
    asm("{ .reg .u64 t; cvta.to.shared.u64 t, %1; cvt.u32.u64 %0, t; }"
        : "=r"(a) : "l"(p));
    return a;
}
__device__ __forceinline__ void ldsm_x4(uint32_t& r0, uint32_t& r1, uint32_t& r2,
                                        uint32_t& r3, uint32_t addr) {
    asm volatile("ldmatrix.sync.aligned.m8n8.x4.shared.b16 {%0,%1,%2,%3}, [%4];"
                 : "=r"(r0), "=r"(r1), "=r"(r2), "=r"(r3) : "r"(addr));
}
__device__ __forceinline__ void mma16816(float* c, const uint32_t* a,
                                         uint32_t b0, uint32_t b1) {
    asm volatile(
        "mma.sync.aligned.m16n8k16.row.col.f32.bf16.bf16.f32 "
        "{%0,%1,%2,%3},{%4,%5,%6,%7},{%8,%9},{%0,%1,%2,%3};"
        : "+f"(c[0]), "+f"(c[1]), "+f"(c[2]), "+f"(c[3])
        : "r"(a[0]), "r"(a[1]), "r"(a[2]), "r"(a[3]), "r"(b0), "r"(b1));
}
__device__ __forceinline__ void split_bf16(float x, __nv_bfloat16& hi, __nv_bfloat16& lo) {
    hi = __float2bfloat16_rn(x);
    lo = __float2bfloat16_rn(x - __bfloat162float(hi));
}

// ---------------------------------------------------------------------------
// Kernel 1: LN + QKV via bf16x3 mma, plus (z==3) denseW prep blocks.
// (unchanged from R5 — proven)
// ---------------------------------------------------------------------------
#define QS_AH 0u
#define QS_AL 34816u
#define QS_BH 69632u
#define QS_BL 104448u
#define SMEM_QKV 139264

__global__ __launch_bounds__(512) void qkv_mma_kernel(
    const float* __restrict__ s_j,
    const float* __restrict__ ln_g, const float* __restrict__ ln_b,
    const float* __restrict__ Wq, const float* __restrict__ bq,
    const float* __restrict__ Wk, const float* __restrict__ bk,
    const float* __restrict__ Wv, const float* __restrict__ bv,
    const float* __restrict__ denseW, int n_nodes)
{
    const int t = threadIdx.x, lane = t & 31, w = t >> 5;

    if (blockIdx.z == 3) {
        int b = blockIdx.y * 157 + blockIdx.x;
        if (b < OUTC) {
            float wv = denseW[(size_t)t * OUTC + b];
            __nv_bfloat16 hi, lo; split_bf16(wv, hi, lo);
            g_Bhi[b * HF + t] = hi;
            g_Blo[b * HF + t] = lo;
        }
        return;
    }

    extern __shared__ char smc[];
    const uint32_t smb = smem_u32(smc);
    const int m = blockIdx.z;
    const int node0 = blockIdx.x * 128;
    const int ncb = blockIdx.y * 128;
    const float* W = (m == 0) ? Wq : (m == 1) ? Wk : Wv;

    float4 g4 = *(const float4*)&ln_g[lane * 4];
    float4 b4 = *(const float4*)&ln_b[lane * 4];
    #pragma unroll
    for (int nn = 0; nn < 8; nn++) {
        int nl = w * 8 + nn;
        int node = node0 + nl;
        float4 x = make_float4(0.f, 0.f, 0.f, 0.f);
        if (node < n_nodes) x = *(const float4*)&s_j[(size_t)node * F + lane * 4];
        float s  = x.x + x.y + x.z + x.w;
        float s2 = x.x * x.x + x.y * x.y + x.z * x.z + x.w * x.w;
        #pragma unroll
        for (int o = 16; o; o >>= 1) {
            s  += __shfl_xor_sync(0xffffffffu, s,  o);
            s2 += __shfl_xor_sync(0xffffffffu, s2, o);
        }
        float mu = s * (1.f / F);
        float var = s2 * (1.f / F) - mu * mu;
        float rs = rsqrtf(var + 1e-5f);
        float y[4] = {(x.x - mu) * rs * g4.x + b4.x, (x.y - mu) * rs * g4.y + b4.y,
                      (x.z - mu) * rs * g4.z + b4.z, (x.w - mu) * rs * g4.w + b4.w};
        __nv_bfloat16 h0, l0, h1, l1, h2, l2, h3, l3;
        split_bf16(y[0], h0, l0); split_bf16(y[1], h1, l1);
        split_bf16(y[2], h2, l2); split_bf16(y[3], h3, l3);
        uint32_t off = (uint32_t)(nl * 136 + lane * 4) * 2u;
        __nv_bfloat162 hp0 = __halves2bfloat162(h0, h1), hp1 = __halves2bfloat162(h2, h3);
        __nv_bfloat162 lp0 = __halves2bfloat162(l0, l1), lp1 = __halves2bfloat162(l2, l3);
        uint2 hv, lv;
        hv.x = *(uint32_t*)&hp0; hv.y = *(uint32_t*)&hp1;
        lv.x = *(uint32_t*)&lp0; lv.y = *(uint32_t*)&lp1;
        *(uint2*)(smc + QS_AH + off) = hv;
        *(uint2*)(smc + QS_AL + off) = lv;
    }

    #pragma unroll
    for (int it = 0; it < 8; it++) {
        int s = it * 512 + t;
        int k = s >> 5, n4 = (s & 31) * 4;
        float4 wv = *(const float4*)&W[(size_t)k * HF + ncb + n4];
        float vv[4] = {wv.x, wv.y, wv.z, wv.w};
        #pragma unroll
        for (int i = 0; i < 4; i++) {
            __nv_bfloat16 hi, lo; split_bf16(vv[i], hi, lo);
            uint32_t off = (uint32_t)((n4 + i) * 136 + k) * 2u;
            *(__nv_bfloat16*)(smc + QS_BH + off) = hi;
            *(__nv_bfloat16*)(smc + QS_BL + off) = lo;
        }
    }
    __syncthreads();

    const int wm3 = w >> 1, wn3 = w & 1;
    float acc[8][4];
    #pragma unroll
    for (int f = 0; f < 8; f++)
        #pragma unroll
        for (int q = 0; q < 4; q++) acc[f][q] = 0.f;

    const uint32_t aoff = (uint32_t)((wm3 * 16 + (lane & 15)) * 136 + (lane >> 4) * 8) * 2u;
    const uint32_t brow = (uint32_t)((lane & 7) + ((lane >> 4) & 1) * 8);
    const uint32_t bcof = (uint32_t)(((lane >> 3) & 1) * 8);

    #pragma unroll
    for (int s = 0; s < 8; s++) {
        uint32_t ah[4], al[4];
        ldsm_x4(ah[0], ah[1], ah[2], ah[3], smb + QS_AH + aoff + s * 32);
        ldsm_x4(al[0], al[1], al[2], al[3], smb + QS_AL + aoff + s * 32);
        #pragma unroll
        for (int f = 0; f < 4; f++) {
            uint32_t n0 = (uint32_t)(wn3 * 64 + f * 16);
            uint32_t boff = ((n0 + brow) * 136 + bcof) * 2u + s * 32;
            uint32_t bh[4], bl[4];
            ldsm_x4(bh[0], bh[1], bh[2], bh[3], smb + QS_BH + boff);
            ldsm_x4(bl[0], bl[1], bl[2], bl[3], smb + QS_BL + boff);
            mma16816(acc[2 * f],     ah, bh[0], bh[1]);
            mma16816(acc[2 * f + 1], ah, bh[2], bh[3]);
            mma16816(acc[2 * f],     ah, bl[0], bl[1]);
            mma16816(acc[2 * f + 1], ah, bl[2], bl[3]);
            mma16816(acc[2 * f],     al, bh[0], bh[1]);
            mma16816(acc[2 * f + 1], al, bh[2], bh[3]);
        }
    }

    float* outp = (m == 0) ? g_q : (m == 1) ? g_k : g_v;
    const float* bias = (m == 0) ? bq : (m == 1) ? bk : bv;
    const int g = lane >> 2, tig = lane & 3;
    int na = node0 + wm3 * 16 + g;
    int nb = na + 8;
    #pragma unroll
    for (int f = 0; f < 8; f++) {
        int col = ncb + wn3 * 64 + f * 8 + tig * 2;
        float2 b2 = *(const float2*)&bias[col];
        if (na < n_nodes)
            *(float2*)&outp[(size_t)na * HF + col] =
                make_float2(acc[f][0] + b2.x, acc[f][1] + b2.y);
        if (nb < n_nodes)
            *(float2*)&outp[(size_t)nb * HF + col] =
                make_float2(acc[f][2] + b2.x, acc[f][3] + b2.y);
    }
}

// ---------------------------------------------------------------------------
// Kernel 2: msg production (phases A/B). grid E/64, block 512, 2 CTAs/SM.
// smem floats: dks[16*512] @0, dvs @8192, rbf @16384 (64*20), env @17664, ij @17728
// ---------------------------------------------------------------------------
#define SMEM_MSG 71424

__global__ __launch_bounds__(512, 2) void msg_kernel(
    const float* __restrict__ dist, const int* __restrict__ nbrs,
    const float* __restrict__ dkW, const float* __restrict__ dkb,
    const float* __restrict__ dvW, const float* __restrict__ dvb)
{
    extern __shared__ float sm[];
    float* dks = sm;
    float* dvs = sm + 8192;
    float* rbf = sm + 16384;
    float* env = sm + 17664;
    int*   ij  = (int*)(sm + 17728);

    const int t = threadIdx.x, lane = t & 31, w = t >> 5;
    const int e0 = blockIdx.x * 64;

    if (t < 128) ij[t] = nbrs[(size_t)e0 * 2 + t];
    if (t < 64) {
        float d = dist[e0 + t];
        env[t] = 0.5f * (cospif(d * 0.2f) + 1.f);
    }
    for (int s = t; s < 64 * NRBF; s += 512) {
        int e = s / NRBF, r = s % NRBF;
        float d = dist[e0 + e];
        float u = (d - (float)r * (5.f / 19.f)) * (19.f / 5.f);
        rbf[s] = __expf(-0.5f * u * u);
    }

    float wk[NRBF], wv[NRBF];
    #pragma unroll
    for (int r = 0; r < NRBF; r++) {
        wk[r] = dkW[r * HF + t];
        wv[r] = dvW[r * HF + t];
    }
    const float bk_ = dkb[t];
    const float bv_ = dvb[t];
    __syncthreads();

    for (int qb = 0; qb < 4; qb++) {
        // B0: dk/dv silu for 16 edges
        #pragma unroll 4
        for (int el = 0; el < 16; el++) {
            int e = qb * 16 + el;
            float a = bk_, b = bv_;
            #pragma unroll
            for (int r = 0; r < NRBF; r += 4) {
                float4 rb = *(float4*)&rbf[e * NRBF + r];
                a += rb.x * wk[r] + rb.y * wk[r + 1] + rb.z * wk[r + 2] + rb.w * wk[r + 3];
                b += rb.x * wv[r] + rb.y * wv[r + 1] + rb.z * wv[r + 2] + rb.w * wv[r + 3];
            }
            dks[el * 512 + t] = silu_f(a);
            dvs[el * 512 + t] = silu_f(b);
        }
        __syncthreads();

        // B1: warp = edge (el = w), 4 heads
        {
            int el = w;
            int e  = qb * 16 + el;
            int i  = ij[2 * e];
            int j  = ij[2 * e + 1];
            const float* qp = g_q + (size_t)i * HF;
            const float* kp = g_k + (size_t)j * HF;
            const float* vp = g_v + (size_t)j * HF;
            float envE = env[e];
            #pragma unroll
            for (int h = 0; h < H; h++) {
                int f4 = h * F + lane * 4;
                float4 q4 = *(const float4*)(qp + f4);
                float4 k4 = *(const float4*)(kp + f4);
                float4 dk4 = *(float4*)&dks[el * 512 + f4];
                float s = q4.x * dk4.x * k4.x + q4.y * dk4.y * k4.y
                        + q4.z * dk4.z * k4.z + q4.w * dk4.w * k4.w;
                #pragma unroll
                for (int o = 16; o; o >>= 1) s += __shfl_xor_sync(0xffffffffu, s, o);
                float attn = silu_f(s) * envE;
                float4 v4 = *(const float4*)(vp + f4);
                float4 dv4 = *(float4*)&dvs[el * 512 + f4];
                float m0 = attn * v4.x * dv4.x;
                float m1 = attn * v4.y * dv4.y;
                float m2 = attn * v4.z * dv4.z;
                float m3 = attn * v4.w * dv4.w;
                __nv_bfloat16 h0, l0, h1, l1, h2, l2, h3, l3;
                split_bf16(m0, h0, l0); split_bf16(m1, h1, l1);
                split_bf16(m2, h2, l2); split_bf16(m3, h3, l3);
                __nv_bfloat162 hp0 = __halves2bfloat162(h0, h1);
                __nv_bfloat162 hp1 = __halves2bfloat162(h2, h3);
                __nv_bfloat162 lp0 = __halves2bfloat162(l0, l1);
                __nv_bfloat162 lp1 = __halves2bfloat162(l2, l3);
                uint2 hv, lv;
                hv.x = *(uint32_t*)&hp0; hv.y = *(uint32_t*)&hp1;
                lv.x = *(uint32_t*)&lp0; lv.y = *(uint32_t*)&lp1;
                size_t o8 = (size_t)(e0 + e) * HF + f4;
                *(uint2*)&g_msgh[o8] = hv;
                *(uint2*)&g_msgl[o8] = lv;
            }
        }
        __syncthreads();
    }
}

// ---------------------------------------------------------------------------
// Kernel 3: GEMM out[E,384] = msg[E,512] @ denseW[512,384] + b (bf16x3).
// grid (4 n-splits, E/128), block 256 (8 warps = 8m x 1n of m16 x n96).
// smem: Ahi[128][40] Alo, Bhi[96][40] Blo (bf16)
// ---------------------------------------------------------------------------
#define GS_AH 0u
#define GS_AL 10240u
#define GS_BH 20480u
#define GS_BL 28160u
#define SMEM_GEMM 35840

__global__ __launch_bounds__(256) void gemm_kernel(
    const float* __restrict__ denseb, float* __restrict__ out)
{
    extern __shared__ char smc[];
    const uint32_t smb = smem_u32(smc);
    const int t = threadIdx.x, lane = t & 31, w = t >> 5;
    const int nb = blockIdx.x * 96;
    const int e0 = blockIdx.y * 128;

    float acc[12][4];
    #pragma unroll
    for (int f = 0; f < 12; f++)
        #pragma unroll
        for (int q = 0; q < 4; q++) acc[f][q] = 0.f;

    const uint32_t aoff = (uint32_t)((w * 16 + (lane & 15)) * 40 + (lane >> 4) * 8) * 2u;
    const uint32_t brow = (uint32_t)((lane & 7) + ((lane >> 4) & 1) * 8);
    const uint32_t bcof = (uint32_t)(((lane >> 3) & 1) * 8);

    for (int c = 0; c < 16; c++) {
        __syncthreads();
        // stage A: 128 rows x 4 q x {hi,lo} = 1024 units of 16B
        #pragma unroll
        for (int it = 0; it < 4; it++) {
            int s = it * 256 + t;
            int hi = (s < 512);
            int u = s & 511;
            int row = u >> 2, q = u & 3;
            const __nv_bfloat16* src = hi ? g_msgh : g_msgl;
            uint32_t dst = (hi ? GS_AH : GS_AL) + (uint32_t)(row * 80 + q * 16);
            *(float4*)(smc + dst) =
                *(const float4*)&src[(size_t)(e0 + row) * HF + c * 32 + q * 8];
        }
        // stage B: 96 rows x 4 q x {hi,lo} = 768 units
        #pragma unroll
        for (int it = 0; it < 3; it++) {
            int s = it * 256 + t;
            int hi = (s < 384);
            int u = hi ? s : (s - 384);
            int row = u >> 2, q = u & 3;
            const __nv_bfloat16* src = hi ? g_Bhi : g_Blo;
            uint32_t dst = (hi ? GS_BH : GS_BL) + (uint32_t)(row * 80 + q * 16);
            *(float4*)(smc + dst) =
                *(const float4*)&src[(size_t)(nb + row) * HF + c * 32 + q * 8];
        }
        __syncthreads();

        #pragma unroll
        for (int s = 0; s < 2; s++) {
            uint32_t ah[4], al[4];
            ldsm_x4(ah[0], ah[1], ah[2], ah[3], smb + GS_AH + aoff + s * 32);
            ldsm_x4(al[0], al[1], al[2], al[3], smb + GS_AL + aoff + s * 32);
            #pragma unroll
            for (int f2 = 0; f2 < 6; f2++) {
                uint32_t boff = ((f2 * 16 + brow) * 40 + bcof) * 2u + s * 32;
                uint32_t bh[4], bl[4];
                ldsm_x4(bh[0], bh[1], bh[2], bh[3], smb + GS_BH + boff);
                ldsm_x4(bl[0], bl[1], bl[2], bl[3], smb + GS_BL + boff);
                mma16816(acc[2 * f2],     ah, bh[0], bh[1]);
                mma16816(acc[2 * f2 + 1], ah, bh[2], bh[3]);
                mma16816(acc[2 * f2],     ah, bl[0], bl[1]);
                mma16816(acc[2 * f2 + 1], ah, bl[2], bl[3]);
                mma16816(acc[2 * f2],     al, bh[0], bh[1]);
                mma16816(acc[2 * f2 + 1], al, bh[2], bh[3]);
            }
        }
    }

    const int g = lane >> 2, tig = lane & 3;
    const size_t r0 = (size_t)(e0 + w * 16 + g) * OUTC;
    const size_t r1 = r0 + 8 * OUTC;
    #pragma unroll
    for (int f = 0; f < 12; f++) {
        int col = nb + f * 8 + tig * 2;
        float2 b2 = *(const float2*)&denseb[col];
        *(float2*)&out[r0 + col] = make_float2(acc[f][0] + b2.x, acc[f][1] + b2.y);
        *(float2*)&out[r1 + col] = make_float2(acc[f][2] + b2.x, acc[f][3] + b2.y);
    }
}

// ---------------------------------------------------------------------------
extern "C" void kernel_launch(void* const* d_in, const int* in_sizes, int n_in,
                              void* d_out, int out_size)
{
    const float* s_j    = (const float*)d_in[0];
    const float* dist   = (const float*)d_in[1];
    const int*   nbrs   = (const int*)  d_in[2];
    const float* ln_g   = (const float*)d_in[3];
    const float* ln_b   = (const float*)d_in[4];
    const float* Wq     = (const float*)d_in[5];
    const float* bq     = (const float*)d_in[6];
    const float* Wk     = (const float*)d_in[7];
    const float* bk     = (const float*)d_in[8];
    const float* Wv     = (const float*)d_in[9];
    const float* bv     = (const float*)d_in[10];
    const float* dkW    = (const float*)d_in[11];
    const float* dkb    = (const float*)d_in[12];
    const float* dvW    = (const float*)d_in[13];
    const float* dvb    = (const float*)d_in[14];
    const float* denseW = (const float*)d_in[15];
    const float* denseb = (const float*)d_in[16];
    float* out = (float*)d_out;

    int n_nodes = in_sizes[0] / F;    // 20000
    int n_edges = in_sizes[1];        // 160000

    cudaFuncSetAttribute(qkv_mma_kernel, cudaFuncAttributeMaxDynamicSharedMemorySize, SMEM_QKV);
    cudaFuncSetAttribute(msg_kernel,     cudaFuncAttributeMaxDynamicSharedMemorySize, SMEM_MSG);
    cudaFuncSetAttribute(gemm_kernel,    cudaFuncAttributeMaxDynamicSharedMemorySize, SMEM_GEMM);

    dim3 gq((n_nodes + 127) / 128, 4, 4);
    qkv_mma_kernel<<<gq, 512, SMEM_QKV>>>(s_j, ln_g, ln_b, Wq, bq, Wk, bk, Wv, bv,
                                          denseW, n_nodes);

    msg_kernel<<<n_edges / 64, 512, SMEM_MSG>>>(dist, nbrs, dkW, dkb, dvW, dvb);

    dim3 gg(4, n_edges / 128);
    gemm_kernel<<<gg, 256, SMEM_GEMM>>>(denseb, out);
}

// round 7
// speedup vs baseline: 1.4926x; 1.1807x over previous
#include <cuda_runtime.h>
#include <cuda_bf16.h>
#include <cstdint>

#define F 128
#define H 4
#define HF 512
#define NRBF 20
#define OUTC 384
#define NODES_MAX 20000
#define NEDGE 160000

__device__ float g_q[NODES_MAX * HF];
__device__ float g_k[NODES_MAX * HF];
__device__ float g_v[NODES_MAX * HF];
__device__ __nv_bfloat16 g_Bhi[OUTC * HF];     // denseW^T hi, [n][k]
__device__ __nv_bfloat16 g_Blo[OUTC * HF];     // denseW^T lo, [n][k]
__device__ __nv_bfloat16 g_msgh[NEDGE * HF];   // msg hi, [e][k]
__device__ __nv_bfloat16 g_msgl[NEDGE * HF];   // msg lo, [e][k]

__device__ __forceinline__ float silu_f(float x) {
    return x * __fdividef(1.f, 1.f + __expf(-x));
}
__device__ __forceinline__ uint32_t smem_u32(const void* p) {
    uint32_t a;
    asm("{ .reg .u64 t; cvta.to.shared.u64 t, %1; cvt.u32.u64 %0, t; }"
        : "=r"(a) : "l"(p));
    return a;
}
__device__ __forceinline__ void ldsm_x4(uint32_t& r0, uint32_t& r1, uint32_t& r2,
                                        uint32_t& r3, uint32_t addr) {
    asm volatile("ldmatrix.sync.aligned.m8n8.x4.shared.b16 {%0,%1,%2,%3}, [%4];"
                 : "=r"(r0), "=r"(r1), "=r"(r2), "=r"(r3) : "r"(addr));
}
__device__ __forceinline__ void mma16816(float* c, const uint32_t* a,
                                         uint32_t b0, uint32_t b1) {
    asm volatile(
        "mma.sync.aligned.m16n8k16.row.col.f32.bf16.bf16.f32 "
        "{%0,%1,%2,%3},{%4,%5,%6,%7},{%8,%9},{%0,%1,%2,%3};"
        : "+f"(c[0]), "+f"(c[1]), "+f"(c[2]), "+f"(c[3])
        : "r"(a[0]), "r"(a[1]), "r"(a[2]), "r"(a[3]), "r"(b0), "r"(b1));
}
__device__ __forceinline__ void split_bf16(float x, __nv_bfloat16& hi, __nv_bfloat16& lo) {
    hi = __float2bfloat16_rn(x);
    lo = __float2bfloat16_rn(x - __bfloat162float(hi));
}
__device__ __forceinline__ void cp16(uint32_t saddr, const void* gaddr) {
    asm volatile("cp.async.cg.shared.global [%0], [%1], 16;"
                 :: "r"(saddr), "l"(gaddr));
}
#define CP_COMMIT() asm volatile("cp.async.commit_group;" ::: "memory")
#define CP_WAIT(n)  asm volatile("cp.async.wait_group %0;" :: "n"(n) : "memory")

// ---------------------------------------------------------------------------
// Kernel 1: LN + QKV via bf16x3 mma, plus (z==3) denseW prep blocks. (proven)
// ---------------------------------------------------------------------------
#define QS_AH 0u
#define QS_AL 34816u
#define QS_BH 69632u
#define QS_BL 104448u
#define SMEM_QKV 139264

__global__ __launch_bounds__(512) void qkv_mma_kernel(
    const float* __restrict__ s_j,
    const float* __restrict__ ln_g, const float* __restrict__ ln_b,
    const float* __restrict__ Wq, const float* __restrict__ bq,
    const float* __restrict__ Wk, const float* __restrict__ bk,
    const float* __restrict__ Wv, const float* __restrict__ bv,
    const float* __restrict__ denseW, int n_nodes)
{
    const int t = threadIdx.x, lane = t & 31, w = t >> 5;

    if (blockIdx.z == 3) {
        int b = blockIdx.y * 157 + blockIdx.x;
        if (b < OUTC) {
            float wv = denseW[(size_t)t * OUTC + b];
            __nv_bfloat16 hi, lo; split_bf16(wv, hi, lo);
            g_Bhi[b * HF + t] = hi;
            g_Blo[b * HF + t] = lo;
        }
        return;
    }

    extern __shared__ char smc[];
    const uint32_t smb = smem_u32(smc);
    const int m = blockIdx.z;
    const int node0 = blockIdx.x * 128;
    const int ncb = blockIdx.y * 128;
    const float* W = (m == 0) ? Wq : (m == 1) ? Wk : Wv;

    float4 g4 = *(const float4*)&ln_g[lane * 4];
    float4 b4 = *(const float4*)&ln_b[lane * 4];
    #pragma unroll
    for (int nn = 0; nn < 8; nn++) {
        int nl = w * 8 + nn;
        int node = node0 + nl;
        float4 x = make_float4(0.f, 0.f, 0.f, 0.f);
        if (node < n_nodes) x = *(const float4*)&s_j[(size_t)node * F + lane * 4];
        float s  = x.x + x.y + x.z + x.w;
        float s2 = x.x * x.x + x.y * x.y + x.z * x.z + x.w * x.w;
        #pragma unroll
        for (int o = 16; o; o >>= 1) {
            s  += __shfl_xor_sync(0xffffffffu, s,  o);
            s2 += __shfl_xor_sync(0xffffffffu, s2, o);
        }
        float mu = s * (1.f / F);
        float var = s2 * (1.f / F) - mu * mu;
        float rs = rsqrtf(var + 1e-5f);
        float y[4] = {(x.x - mu) * rs * g4.x + b4.x, (x.y - mu) * rs * g4.y + b4.y,
                      (x.z - mu) * rs * g4.z + b4.z, (x.w - mu) * rs * g4.w + b4.w};
        __nv_bfloat16 h0, l0, h1, l1, h2, l2, h3, l3;
        split_bf16(y[0], h0, l0); split_bf16(y[1], h1, l1);
        split_bf16(y[2], h2, l2); split_bf16(y[3], h3, l3);
        uint32_t off = (uint32_t)(nl * 136 + lane * 4) * 2u;
        __nv_bfloat162 hp0 = __halves2bfloat162(h0, h1), hp1 = __halves2bfloat162(h2, h3);
        __nv_bfloat162 lp0 = __halves2bfloat162(l0, l1), lp1 = __halves2bfloat162(l2, l3);
        uint2 hv, lv;
        hv.x = *(uint32_t*)&hp0; hv.y = *(uint32_t*)&hp1;
        lv.x = *(uint32_t*)&lp0; lv.y = *(uint32_t*)&lp1;
        *(uint2*)(smc + QS_AH + off) = hv;
        *(uint2*)(smc + QS_AL + off) = lv;
    }

    #pragma unroll
    for (int it = 0; it < 8; it++) {
        int s = it * 512 + t;
        int k = s >> 5, n4 = (s & 31) * 4;
        float4 wv = *(const float4*)&W[(size_t)k * HF + ncb + n4];
        float vv[4] = {wv.x, wv.y, wv.z, wv.w};
        #pragma unroll
        for (int i = 0; i < 4; i++) {
            __nv_bfloat16 hi, lo; split_bf16(vv[i], hi, lo);
            uint32_t off = (uint32_t)((n4 + i) * 136 + k) * 2u;
            *(__nv_bfloat16*)(smc + QS_BH + off) = hi;
            *(__nv_bfloat16*)(smc + QS_BL + off) = lo;
        }
    }
    __syncthreads();

    const int wm3 = w >> 1, wn3 = w & 1;
    float acc[8][4];
    #pragma unroll
    for (int f = 0; f < 8; f++)
        #pragma unroll
        for (int q = 0; q < 4; q++) acc[f][q] = 0.f;

    const uint32_t aoff = (uint32_t)((wm3 * 16 + (lane & 15)) * 136 + (lane >> 4) * 8) * 2u;
    const uint32_t brow = (uint32_t)((lane & 7) + ((lane >> 4) & 1) * 8);
    const uint32_t bcof = (uint32_t)(((lane >> 3) & 1) * 8);

    #pragma unroll
    for (int s = 0; s < 8; s++) {
        uint32_t ah[4], al[4];
        ldsm_x4(ah[0], ah[1], ah[2], ah[3], smb + QS_AH + aoff + s * 32);
        ldsm_x4(al[0], al[1], al[2], al[3], smb + QS_AL + aoff + s * 32);
        #pragma unroll
        for (int f = 0; f < 4; f++) {
            uint32_t n0 = (uint32_t)(wn3 * 64 + f * 16);
            uint32_t boff = ((n0 + brow) * 136 + bcof) * 2u + s * 32;
            uint32_t bh[4], bl[4];
            ldsm_x4(bh[0], bh[1], bh[2], bh[3], smb + QS_BH + boff);
            ldsm_x4(bl[0], bl[1], bl[2], bl[3], smb + QS_BL + boff);
            mma16816(acc[2 * f],     ah, bh[0], bh[1]);
            mma16816(acc[2 * f + 1], ah, bh[2], bh[3]);
            mma16816(acc[2 * f],     ah, bl[0], bl[1]);
            mma16816(acc[2 * f + 1], ah, bl[2], bl[3]);
            mma16816(acc[2 * f],     al, bh[0], bh[1]);
            mma16816(acc[2 * f + 1], al, bh[2], bh[3]);
        }
    }

    float* outp = (m == 0) ? g_q : (m == 1) ? g_k : g_v;
    const float* bias = (m == 0) ? bq : (m == 1) ? bk : bv;
    const int g = lane >> 2, tig = lane & 3;
    int na = node0 + wm3 * 16 + g;
    int nb2 = na + 8;
    #pragma unroll
    for (int f = 0; f < 8; f++) {
        int col = ncb + wn3 * 64 + f * 8 + tig * 2;
        float2 b2 = *(const float2*)&bias[col];
        if (na < n_nodes)
            *(float2*)&outp[(size_t)na * HF + col] =
                make_float2(acc[f][0] + b2.x, acc[f][1] + b2.y);
        if (nb2 < n_nodes)
            *(float2*)&outp[(size_t)nb2 * HF + col] =
                make_float2(acc[f][2] + b2.x, acc[f][3] + b2.y);
    }
}

// ---------------------------------------------------------------------------
// Kernel 2: msg production (unchanged from R6 — proven)
// ---------------------------------------------------------------------------
#define SMEM_MSG 71424

__global__ __launch_bounds__(512, 2) void msg_kernel(
    const float* __restrict__ dist, const int* __restrict__ nbrs,
    const float* __restrict__ dkW, const float* __restrict__ dkb,
    const float* __restrict__ dvW, const float* __restrict__ dvb)
{
    extern __shared__ float sm[];
    float* dks = sm;
    float* dvs = sm + 8192;
    float* rbf = sm + 16384;
    float* env = sm + 17664;
    int*   ij  = (int*)(sm + 17728);

    const int t = threadIdx.x, lane = t & 31, w = t >> 5;
    const int e0 = blockIdx.x * 64;

    if (t < 128) ij[t] = nbrs[(size_t)e0 * 2 + t];
    if (t < 64) {
        float d = dist[e0 + t];
        env[t] = 0.5f * (cospif(d * 0.2f) + 1.f);
    }
    for (int s = t; s < 64 * NRBF; s += 512) {
        int e = s / NRBF, r = s % NRBF;
        float d = dist[e0 + e];
        float u = (d - (float)r * (5.f / 19.f)) * (19.f / 5.f);
        rbf[s] = __expf(-0.5f * u * u);
    }

    float wk[NRBF], wv[NRBF];
    #pragma unroll
    for (int r = 0; r < NRBF; r++) {
        wk[r] = dkW[r * HF + t];
        wv[r] = dvW[r * HF + t];
    }
    const float bk_ = dkb[t];
    const float bv_ = dvb[t];
    __syncthreads();

    for (int qb = 0; qb < 4; qb++) {
        #pragma unroll 4
        for (int el = 0; el < 16; el++) {
            int e = qb * 16 + el;
            float a = bk_, b = bv_;
            #pragma unroll
            for (int r = 0; r < NRBF; r += 4) {
                float4 rb = *(float4*)&rbf[e * NRBF + r];
                a += rb.x * wk[r] + rb.y * wk[r + 1] + rb.z * wk[r + 2] + rb.w * wk[r + 3];
                b += rb.x * wv[r] + rb.y * wv[r + 1] + rb.z * wv[r + 2] + rb.w * wv[r + 3];
            }
            dks[el * 512 + t] = silu_f(a);
            dvs[el * 512 + t] = silu_f(b);
        }
        __syncthreads();

        {
            int el = w;
            int e  = qb * 16 + el;
            int i  = ij[2 * e];
            int j  = ij[2 * e + 1];
            const float* qp = g_q + (size_t)i * HF;
            const float* kp = g_k + (size_t)j * HF;
            const float* vp = g_v + (size_t)j * HF;
            float envE = env[e];
            #pragma unroll
            for (int h = 0; h < H; h++) {
                int f4 = h * F + lane * 4;
                float4 q4 = *(const float4*)(qp + f4);
                float4 k4 = *(const float4*)(kp + f4);
                float4 dk4 = *(float4*)&dks[el * 512 + f4];
                float s = q4.x * dk4.x * k4.x + q4.y * dk4.y * k4.y
                        + q4.z * dk4.z * k4.z + q4.w * dk4.w * k4.w;
                #pragma unroll
                for (int o = 16; o; o >>= 1) s += __shfl_xor_sync(0xffffffffu, s, o);
                float attn = silu_f(s) * envE;
                float4 v4 = *(const float4*)(vp + f4);
                float4 dv4 = *(float4*)&dvs[el * 512 + f4];
                float m0 = attn * v4.x * dv4.x;
                float m1 = attn * v4.y * dv4.y;
                float m2 = attn * v4.z * dv4.z;
                float m3 = attn * v4.w * dv4.w;
                __nv_bfloat16 h0, l0, h1, l1, h2, l2, h3, l3;
                split_bf16(m0, h0, l0); split_bf16(m1, h1, l1);
                split_bf16(m2, h2, l2); split_bf16(m3, h3, l3);
                __nv_bfloat162 hp0 = __halves2bfloat162(h0, h1);
                __nv_bfloat162 hp1 = __halves2bfloat162(h2, h3);
                __nv_bfloat162 lp0 = __halves2bfloat162(l0, l1);
                __nv_bfloat162 lp1 = __halves2bfloat162(l2, l3);
                uint2 hv, lv;
                hv.x = *(uint32_t*)&hp0; hv.y = *(uint32_t*)&hp1;
                lv.x = *(uint32_t*)&lp0; lv.y = *(uint32_t*)&lp1;
                size_t o8 = (size_t)(e0 + e) * HF + f4;
                *(uint2*)&g_msgh[o8] = hv;
                *(uint2*)&g_msgl[o8] = lv;
            }
        }
        __syncthreads();
    }
}

// ---------------------------------------------------------------------------
// Kernel 3: GEMM with cp.async double-buffered pipeline.
// grid (4 n-splits, E/128), block 256. 2 smem stages of 35840 B.
// stage layout: AH 0 (128x80B), AL 10240, BH 20480 (96x80B), BL 28160.
// ---------------------------------------------------------------------------
#define GST 35840u
#define G_AH 0u
#define G_AL 10240u
#define G_BH 20480u
#define G_BL 28160u
#define SMEM_GEMM (2 * 35840)

__device__ __forceinline__ void gemm_load_chunk(
    uint32_t sb, int t, int e0, int nb, int c)
{
    // A: 1024 x 16B  (hi: 512, lo: 512)
    #pragma unroll
    for (int it = 0; it < 4; it++) {
        int s = it * 256 + t;
        int hi = (s < 512);
        int u = s & 511;
        int row = u >> 2, q = u & 3;
        const __nv_bfloat16* src = hi ? g_msgh : g_msgl;
        uint32_t dst = sb + (hi ? G_AH : G_AL) + (uint32_t)(row * 80 + q * 16);
        cp16(dst, &src[(size_t)(e0 + row) * HF + c * 32 + q * 8]);
    }
    // B: 768 x 16B
    #pragma unroll
    for (int it = 0; it < 3; it++) {
        int s = it * 256 + t;
        int hi = (s < 384);
        int u = hi ? s : (s - 384);
        int row = u >> 2, q = u & 3;
        const __nv_bfloat16* src = hi ? g_Bhi : g_Blo;
        uint32_t dst = sb + (hi ? G_BH : G_BL) + (uint32_t)(row * 80 + q * 16);
        cp16(dst, &src[(size_t)(nb + row) * HF + c * 32 + q * 8]);
    }
}

__global__ __launch_bounds__(256) void gemm_kernel(
    const float* __restrict__ denseb, float* __restrict__ out)
{
    extern __shared__ char smc[];
    const uint32_t smb = smem_u32(smc);
    const int t = threadIdx.x, lane = t & 31, w = t >> 5;
    const int nb = blockIdx.x * 96;
    const int e0 = blockIdx.y * 128;

    float acc[12][4];
    #pragma unroll
    for (int f = 0; f < 12; f++)
        #pragma unroll
        for (int q = 0; q < 4; q++) acc[f][q] = 0.f;

    const uint32_t aoff = (uint32_t)((w * 16 + (lane & 15)) * 40 + (lane >> 4) * 8) * 2u;
    const uint32_t brow = (uint32_t)((lane & 7) + ((lane >> 4) & 1) * 8);
    const uint32_t bcof = (uint32_t)(((lane >> 3) & 1) * 8);

    // prologue: stage chunk 0
    gemm_load_chunk(smb, t, e0, nb, 0);
    CP_COMMIT();

    for (int c = 0; c < 16; c++) {
        if (c < 15) {
            gemm_load_chunk(smb + ((c + 1) & 1) * GST, t, e0, nb, c + 1);
            CP_COMMIT();
            CP_WAIT(1);
        } else {
            CP_WAIT(0);
        }
        __syncthreads();

        const uint32_t sb = smb + (c & 1) * GST;
        #pragma unroll
        for (int s = 0; s < 2; s++) {
            uint32_t ah[4], al[4];
            ldsm_x4(ah[0], ah[1], ah[2], ah[3], sb + G_AH + aoff + s * 32);
            ldsm_x4(al[0], al[1], al[2], al[3], sb + G_AL + aoff + s * 32);
            #pragma unroll
            for (int f2 = 0; f2 < 6; f2++) {
                uint32_t boff = ((f2 * 16 + brow) * 40 + bcof) * 2u + s * 32;
                uint32_t bh[4], bl[4];
                ldsm_x4(bh[0], bh[1], bh[2], bh[3], sb + G_BH + boff);
                ldsm_x4(bl[0], bl[1], bl[2], bl[3], sb + G_BL + boff);
                mma16816(acc[2 * f2],     ah, bh[0], bh[1]);
                mma16816(acc[2 * f2 + 1], ah, bh[2], bh[3]);
                mma16816(acc[2 * f2],     ah, bl[0], bl[1]);
                mma16816(acc[2 * f2 + 1], ah, bl[2], bl[3]);
                mma16816(acc[2 * f2],     al, bh[0], bh[1]);
                mma16816(acc[2 * f2 + 1], al, bh[2], bh[3]);
            }
        }
        __syncthreads();
    }

    const int g = lane >> 2, tig = lane & 3;
    const size_t r0 = (size_t)(e0 + w * 16 + g) * OUTC;
    const size_t r1 = r0 + 8 * OUTC;
    #pragma unroll
    for (int f = 0; f < 12; f++) {
        int col = nb + f * 8 + tig * 2;
        float2 b2 = *(const float2*)&denseb[col];
        *(float2*)&out[r0 + col] = make_float2(acc[f][0] + b2.x, acc[f][1] + b2.y);
        *(float2*)&out[r1 + col] = make_float2(acc[f][2] + b2.x, acc[f][3] + b2.y);
    }
}

// ---------------------------------------------------------------------------
extern "C" void kernel_launch(void* const* d_in, const int* in_sizes, int n_in,
                              void* d_out, int out_size)
{
    const float* s_j    = (const float*)d_in[0];
    const float* dist   = (const float*)d_in[1];
    const int*   nbrs   = (const int*)  d_in[2];
    const float* ln_g   = (const float*)d_in[3];
    const float* ln_b   = (const float*)d_in[4];
    const float* Wq     = (const float*)d_in[5];
    const float* bq     = (const float*)d_in[6];
    const float* Wk     = (const float*)d_in[7];
    const float* bk     = (const float*)d_in[8];
    const float* Wv     = (const float*)d_in[9];
    const float* bv     = (const float*)d_in[10];
    const float* dkW    = (const float*)d_in[11];
    const float* dkb    = (const float*)d_in[12];
    const float* dvW    = (const float*)d_in[13];
    const float* dvb    = (const float*)d_in[14];
    const float* denseW = (const float*)d_in[15];
    const float* denseb = (const float*)d_in[16];
    float* out = (float*)d_out;

    int n_nodes = in_sizes[0] / F;    // 20000
    int n_edges = in_sizes[1];        // 160000

    cudaFuncSetAttribute(qkv_mma_kernel, cudaFuncAttributeMaxDynamicSharedMemorySize, SMEM_QKV);
    cudaFuncSetAttribute(msg_kernel,     cudaFuncAttributeMaxDynamicSharedMemorySize, SMEM_MSG);
    cudaFuncSetAttribute(gemm_kernel,    cudaFuncAttributeMaxDynamicSharedMemorySize, SMEM_GEMM);

    dim3 gq((n_nodes + 127) / 128, 4, 4);
    qkv_mma_kernel<<<gq, 512, SMEM_QKV>>>(s_j, ln_g, ln_b, Wq, bq, Wk, bk, Wv, bv,
                                          denseW, n_nodes);

    msg_kernel<<<n_edges / 64, 512, SMEM_MSG>>>(dist, nbrs, dkW, dkb, dvW, dvb);

    dim3 gg(4, n_edges / 128);
    gemm_kernel<<<gg, 256, SMEM_GEMM>>>(denseb, out);
}

// round 8
// speedup vs baseline: 1.4972x; 1.0031x over previous
#include <cuda_runtime.h>
#include <cuda_bf16.h>
#include <cstdint>

#define F 128
#define H 4
#define HF 512
#define NRBF 20
#define OUTC 384
#define NODES_MAX 20000
#define NEDGE 160000
#define ECHUNK 32000

__device__ float g_q[NODES_MAX * HF];
__device__ float g_k[NODES_MAX * HF];
__device__ float g_v[NODES_MAX * HF];
__device__ __nv_bfloat16 g_Bhi[OUTC * HF];
__device__ __nv_bfloat16 g_Blo[OUTC * HF];
__device__ __nv_bfloat16 g_msgh[NEDGE * HF];
__device__ __nv_bfloat16 g_msgl[NEDGE * HF];

__device__ __forceinline__ float silu_f(float x) {
    return x * __fdividef(1.f, 1.f + __expf(-x));
}
__device__ __forceinline__ uint32_t smem_u32(const void* p) {
    uint32_t a;
    asm("{ .reg .u64 t; cvta.to.shared.u64 t, %1; cvt.u32.u64 %0, t; }"
        : "=r"(a) : "l"(p));
    return a;
}
__device__ __forceinline__ void ldsm_x4(uint32_t& r0, uint32_t& r1, uint32_t& r2,
                                        uint32_t& r3, uint32_t addr) {
    asm volatile("ldmatrix.sync.aligned.m8n8.x4.shared.b16 {%0,%1,%2,%3}, [%4];"
                 : "=r"(r0), "=r"(r1), "=r"(r2), "=r"(r3) : "r"(addr));
}
__device__ __forceinline__ void mma16816(float* c, const uint32_t* a,
                                         uint32_t b0, uint32_t b1) {
    asm volatile(
        "mma.sync.aligned.m16n8k16.row.col.f32.bf16.bf16.f32 "
        "{%0,%1,%2,%3},{%4,%5,%6,%7},{%8,%9},{%0,%1,%2,%3};"
        : "+f"(c[0]), "+f"(c[1]), "+f"(c[2]), "+f"(c[3])
        : "r"(a[0]), "r"(a[1]), "r"(a[2]), "r"(a[3]), "r"(b0), "r"(b1));
}
__device__ __forceinline__ void split_bf16(float x, __nv_bfloat16& hi, __nv_bfloat16& lo) {
    hi = __float2bfloat16_rn(x);
    lo = __float2bfloat16_rn(x - __bfloat162float(hi));
}
__device__ __forceinline__ void cp16(uint32_t saddr, const void* gaddr) {
    asm volatile("cp.async.cg.shared.global [%0], [%1], 16;"
                 :: "r"(saddr), "l"(gaddr));
}
#define CP_COMMIT() asm volatile("cp.async.commit_group;" ::: "memory")
#define CP_WAIT(n)  asm volatile("cp.async.wait_group %0;" :: "n"(n) : "memory")

// ---------------------------------------------------------------------------
// Kernel 1: LN + QKV via bf16x3 mma, plus (z==3) denseW prep blocks.
// ---------------------------------------------------------------------------
#define QS_AH 0u
#define QS_AL 34816u
#define QS_BH 69632u
#define QS_BL 104448u
#define SMEM_QKV 139264

__global__ __launch_bounds__(512) void qkv_mma_kernel(
    const float* __restrict__ s_j,
    const float* __restrict__ ln_g, const float* __restrict__ ln_b,
    const float* __restrict__ Wq, const float* __restrict__ bq,
    const float* __restrict__ Wk, const float* __restrict__ bk,
    const float* __restrict__ Wv, const float* __restrict__ bv,
    const float* __restrict__ denseW, int n_nodes)
{
    const int t = threadIdx.x, lane = t & 31, w = t >> 5;

    if (blockIdx.z == 3) {
        int b = blockIdx.y * 157 + blockIdx.x;
        if (b < OUTC) {
            float wv = denseW[(size_t)t * OUTC + b];
            __nv_bfloat16 hi, lo; split_bf16(wv, hi, lo);
            g_Bhi[b * HF + t] = hi;
            g_Blo[b * HF + t] = lo;
        }
        return;
    }

    extern __shared__ char smc[];
    const uint32_t smb = smem_u32(smc);
    const int m = blockIdx.z;
    const int node0 = blockIdx.x * 128;
    const int ncb = blockIdx.y * 128;
    const float* W = (m == 0) ? Wq : (m == 1) ? Wk : Wv;

    float4 g4 = *(const float4*)&ln_g[lane * 4];
    float4 b4 = *(const float4*)&ln_b[lane * 4];
    #pragma unroll
    for (int nn = 0; nn < 8; nn++) {
        int nl = w * 8 + nn;
        int node = node0 + nl;
        float4 x = make_float4(0.f, 0.f, 0.f, 0.f);
        if (node < n_nodes) x = *(const float4*)&s_j[(size_t)node * F + lane * 4];
        float s  = x.x + x.y + x.z + x.w;
        float s2 = x.x * x.x + x.y * x.y + x.z * x.z + x.w * x.w;
        #pragma unroll
        for (int o = 16; o; o >>= 1) {
            s  += __shfl_xor_sync(0xffffffffu, s,  o);
            s2 += __shfl_xor_sync(0xffffffffu, s2, o);
        }
        float mu = s * (1.f / F);
        float var = s2 * (1.f / F) - mu * mu;
        float rs = rsqrtf(var + 1e-5f);
        float y[4] = {(x.x - mu) * rs * g4.x + b4.x, (x.y - mu) * rs * g4.y + b4.y,
                      (x.z - mu) * rs * g4.z + b4.z, (x.w - mu) * rs * g4.w + b4.w};
        __nv_bfloat16 h0, l0, h1, l1, h2, l2, h3, l3;
        split_bf16(y[0], h0, l0); split_bf16(y[1], h1, l1);
        split_bf16(y[2], h2, l2); split_bf16(y[3], h3, l3);
        uint32_t off = (uint32_t)(nl * 136 + lane * 4) * 2u;
        __nv_bfloat162 hp0 = __halves2bfloat162(h0, h1), hp1 = __halves2bfloat162(h2, h3);
        __nv_bfloat162 lp0 = __halves2bfloat162(l0, l1), lp1 = __halves2bfloat162(l2, l3);
        uint2 hv, lv;
        hv.x = *(uint32_t*)&hp0; hv.y = *(uint32_t*)&hp1;
        lv.x = *(uint32_t*)&lp0; lv.y = *(uint32_t*)&lp1;
        *(uint2*)(smc + QS_AH + off) = hv;
        *(uint2*)(smc + QS_AL + off) = lv;
    }

    // B tile staging: thread owns (n, k-quad). Coalesced LDG.32 per k-row,
    // 2x STS.64 per slot (was 64 scalar 2B STS with 16-way conflicts).
    #pragma unroll
    for (int it = 0; it < 8; it++) {
        int s = it * 512 + t;
        int n = s & 127, kq = s >> 7;      // kq 0..31
        const float* wp = &W[(size_t)(kq * 4) * HF + ncb + n];
        float w0 = wp[0], w1 = wp[HF], w2 = wp[2 * HF], w3 = wp[3 * HF];
        __nv_bfloat16 h0, l0, h1, l1, h2, l2, h3, l3;
        split_bf16(w0, h0, l0); split_bf16(w1, h1, l1);
        split_bf16(w2, h2, l2); split_bf16(w3, h3, l3);
        __nv_bfloat162 hp0 = __halves2bfloat162(h0, h1), hp1 = __halves2bfloat162(h2, h3);
        __nv_bfloat162 lp0 = __halves2bfloat162(l0, l1), lp1 = __halves2bfloat162(l2, l3);
        uint32_t off = (uint32_t)(n * 136 + kq * 4) * 2u;
        uint2 hv, lv;
        hv.x = *(uint32_t*)&hp0; hv.y = *(uint32_t*)&hp1;
        lv.x = *(uint32_t*)&lp0; lv.y = *(uint32_t*)&lp1;
        *(uint2*)(smc + QS_BH + off) = hv;
        *(uint2*)(smc + QS_BL + off) = lv;
    }
    __syncthreads();

    const int wm3 = w >> 1, wn3 = w & 1;
    float acc[8][4];
    #pragma unroll
    for (int f = 0; f < 8; f++)
        #pragma unroll
        for (int q = 0; q < 4; q++) acc[f][q] = 0.f;

    const uint32_t aoff = (uint32_t)((wm3 * 16 + (lane & 15)) * 136 + (lane >> 4) * 8) * 2u;
    const uint32_t brow = (uint32_t)((lane & 7) + ((lane >> 4) & 1) * 8);
    const uint32_t bcof = (uint32_t)(((lane >> 3) & 1) * 8);

    #pragma unroll
    for (int s = 0; s < 8; s++) {
        uint32_t ah[4], al[4];
        ldsm_x4(ah[0], ah[1], ah[2], ah[3], smb + QS_AH + aoff + s * 32);
        ldsm_x4(al[0], al[1], al[2], al[3], smb + QS_AL + aoff + s * 32);
        #pragma unroll
        for (int f = 0; f < 4; f++) {
            uint32_t n0 = (uint32_t)(wn3 * 64 + f * 16);
            uint32_t boff = ((n0 + brow) * 136 + bcof) * 2u + s * 32;
            uint32_t bh[4], bl[4];
            ldsm_x4(bh[0], bh[1], bh[2], bh[3], smb + QS_BH + boff);
            ldsm_x4(bl[0], bl[1], bl[2], bl[3], smb + QS_BL + boff);
            mma16816(acc[2 * f],     ah, bh[0], bh[1]);
            mma16816(acc[2 * f + 1], ah, bh[2], bh[3]);
            mma16816(acc[2 * f],     ah, bl[0], bl[1]);
            mma16816(acc[2 * f + 1], ah, bl[2], bl[3]);
            mma16816(acc[2 * f],     al, bh[0], bh[1]);
            mma16816(acc[2 * f + 1], al, bh[2], bh[3]);
        }
    }

    float* outp = (m == 0) ? g_q : (m == 1) ? g_k : g_v;
    const float* bias = (m == 0) ? bq : (m == 1) ? bk : bv;
    const int g = lane >> 2, tig = lane & 3;
    int na = node0 + wm3 * 16 + g;
    int nb2 = na + 8;
    #pragma unroll
    for (int f = 0; f < 8; f++) {
        int col = ncb + wn3 * 64 + f * 8 + tig * 2;
        float2 b2 = *(const float2*)&bias[col];
        if (na < n_nodes)
            *(float2*)&outp[(size_t)na * HF + col] =
                make_float2(acc[f][0] + b2.x, acc[f][1] + b2.y);
        if (nb2 < n_nodes)
            *(float2*)&outp[(size_t)nb2 * HF + col] =
                make_float2(acc[f][2] + b2.x, acc[f][3] + b2.y);
    }
}

// ---------------------------------------------------------------------------
// Kernel 2: msg production (chunked)
// ---------------------------------------------------------------------------
#define SMEM_MSG 71424

__global__ __launch_bounds__(512, 2) void msg_kernel(
    const float* __restrict__ dist, const int* __restrict__ nbrs,
    const float* __restrict__ dkW, const float* __restrict__ dkb,
    const float* __restrict__ dvW, const float* __restrict__ dvb,
    int e_base)
{
    extern __shared__ float sm[];
    float* dks = sm;
    float* dvs = sm + 8192;
    float* rbf = sm + 16384;
    float* env = sm + 17664;
    int*   ij  = (int*)(sm + 17728);

    const int t = threadIdx.x, lane = t & 31, w = t >> 5;
    const int e0 = e_base + blockIdx.x * 64;

    if (t < 128) ij[t] = nbrs[(size_t)e0 * 2 + t];
    if (t < 64) {
        float d = dist[e0 + t];
        env[t] = 0.5f * (cospif(d * 0.2f) + 1.f);
    }
    for (int s = t; s < 64 * NRBF; s += 512) {
        int e = s / NRBF, r = s % NRBF;
        float d = dist[e0 + e];
        float u = (d - (float)r * (5.f / 19.f)) * (19.f / 5.f);
        rbf[s] = __expf(-0.5f * u * u);
    }

    float wk[NRBF], wv[NRBF];
    #pragma unroll
    for (int r = 0; r < NRBF; r++) {
        wk[r] = dkW[r * HF + t];
        wv[r] = dvW[r * HF + t];
    }
    const float bk_ = dkb[t];
    const float bv_ = dvb[t];
    __syncthreads();

    for (int qb = 0; qb < 4; qb++) {
        #pragma unroll 4
        for (int el = 0; el < 16; el++) {
            int e = qb * 16 + el;
            float a = bk_, b = bv_;
            #pragma unroll
            for (int r = 0; r < NRBF; r += 4) {
                float4 rb = *(float4*)&rbf[e * NRBF + r];
                a += rb.x * wk[r] + rb.y * wk[r + 1] + rb.z * wk[r + 2] + rb.w * wk[r + 3];
                b += rb.x * wv[r] + rb.y * wv[r + 1] + rb.z * wv[r + 2] + rb.w * wv[r + 3];
            }
            dks[el * 512 + t] = silu_f(a);
            dvs[el * 512 + t] = silu_f(b);
        }
        __syncthreads();

        {
            int el = w;
            int e  = qb * 16 + el;
            int i  = ij[2 * e];
            int j  = ij[2 * e + 1];
            const float* qp = g_q + (size_t)i * HF;
            const float* kp = g_k + (size_t)j * HF;
            const float* vp = g_v + (size_t)j * HF;
            float envE = env[e];
            #pragma unroll
            for (int h = 0; h < H; h++) {
                int f4 = h * F + lane * 4;
                float4 q4 = *(const float4*)(qp + f4);
                float4 k4 = *(const float4*)(kp + f4);
                float4 dk4 = *(float4*)&dks[el * 512 + f4];
                float s = q4.x * dk4.x * k4.x + q4.y * dk4.y * k4.y
                        + q4.z * dk4.z * k4.z + q4.w * dk4.w * k4.w;
                #pragma unroll
                for (int o = 16; o; o >>= 1) s += __shfl_xor_sync(0xffffffffu, s, o);
                float attn = silu_f(s) * envE;
                float4 v4 = *(const float4*)(vp + f4);
                float4 dv4 = *(float4*)&dvs[el * 512 + f4];
                float m0 = attn * v4.x * dv4.x;
                float m1 = attn * v4.y * dv4.y;
                float m2 = attn * v4.z * dv4.z;
                float m3 = attn * v4.w * dv4.w;
                __nv_bfloat16 h0, l0, h1, l1, h2, l2, h3, l3;
                split_bf16(m0, h0, l0); split_bf16(m1, h1, l1);
                split_bf16(m2, h2, l2); split_bf16(m3, h3, l3);
                __nv_bfloat162 hp0 = __halves2bfloat162(h0, h1);
                __nv_bfloat162 hp1 = __halves2bfloat162(h2, h3);
                __nv_bfloat162 lp0 = __halves2bfloat162(l0, l1);
                __nv_bfloat162 lp1 = __halves2bfloat162(l2, l3);
                uint2 hv, lv;
                hv.x = *(uint32_t*)&hp0; hv.y = *(uint32_t*)&hp1;
                lv.x = *(uint32_t*)&lp0; lv.y = *(uint32_t*)&lp1;
                size_t o8 = (size_t)(e0 + e) * HF + f4;
                *(uint2*)&g_msgh[o8] = hv;
                *(uint2*)&g_msgl[o8] = lv;
            }
        }
        __syncthreads();
    }
}

// ---------------------------------------------------------------------------
// Kernel 3: GEMM with cp.async double-buffered pipeline (chunked)
// ---------------------------------------------------------------------------
#define GST 35840u
#define G_AH 0u
#define G_AL 10240u
#define G_BH 20480u
#define G_BL 28160u
#define SMEM_GEMM (2 * 35840)

__device__ __forceinline__ void gemm_load_chunk(
    uint32_t sb, int t, int e0, int nb, int c)
{
    #pragma unroll
    for (int it = 0; it < 4; it++) {
        int s = it * 256 + t;
        int hi = (s < 512);
        int u = s & 511;
        int row = u >> 2, q = u & 3;
        const __nv_bfloat16* src = hi ? g_msgh : g_msgl;
        uint32_t dst = sb + (hi ? G_AH : G_AL) + (uint32_t)(row * 80 + q * 16);
        cp16(dst, &src[(size_t)(e0 + row) * HF + c * 32 + q * 8]);
    }
    #pragma unroll
    for (int it = 0; it < 3; it++) {
        int s = it * 256 + t;
        int hi = (s < 384);
        int u = hi ? s : (s - 384);
        int row = u >> 2, q = u & 3;
        const __nv_bfloat16* src = hi ? g_Bhi : g_Blo;
        uint32_t dst = sb + (hi ? G_BH : G_BL) + (uint32_t)(row * 80 + q * 16);
        cp16(dst, &src[(size_t)(nb + row) * HF + c * 32 + q * 8]);
    }
}

__global__ __launch_bounds__(256) void gemm_kernel(
    const float* __restrict__ denseb, float* __restrict__ out, int e_base)
{
    extern __shared__ char smc[];
    const uint32_t smb = smem_u32(smc);
    const int t = threadIdx.x, lane = t & 31, w = t >> 5;
    const int nb = blockIdx.x * 96;
    const int e0 = e_base + blockIdx.y * 128;

    float acc[12][4];
    #pragma unroll
    for (int f = 0; f < 12; f++)
        #pragma unroll
        for (int q = 0; q < 4; q++) acc[f][q] = 0.f;

    const uint32_t aoff = (uint32_t)((w * 16 + (lane & 15)) * 40 + (lane >> 4) * 8) * 2u;
    const uint32_t brow = (uint32_t)((lane & 7) + ((lane >> 4) & 1) * 8);
    const uint32_t bcof = (uint32_t)(((lane >> 3) & 1) * 8);

    gemm_load_chunk(smb, t, e0, nb, 0);
    CP_COMMIT();

    for (int c = 0; c < 16; c++) {
        if (c < 15) {
            gemm_load_chunk(smb + ((c + 1) & 1) * GST, t, e0, nb, c + 1);
            CP_COMMIT();
            CP_WAIT(1);
        } else {
            CP_WAIT(0);
        }
        __syncthreads();

        const uint32_t sb = smb + (c & 1) * GST;
        #pragma unroll
        for (int s = 0; s < 2; s++) {
            uint32_t ah[4], al[4];
            ldsm_x4(ah[0], ah[1], ah[2], ah[3], sb + G_AH + aoff + s * 32);
            ldsm_x4(al[0], al[1], al[2], al[3], sb + G_AL + aoff + s * 32);
            #pragma unroll
            for (int f2 = 0; f2 < 6; f2++) {
                uint32_t boff = ((f2 * 16 + brow) * 40 + bcof) * 2u + s * 32;
                uint32_t bh[4], bl[4];
                ldsm_x4(bh[0], bh[1], bh[2], bh[3], sb + G_BH + boff);
                ldsm_x4(bl[0], bl[1], bl[2], bl[3], sb + G_BL + boff);
                mma16816(acc[2 * f2],     ah, bh[0], bh[1]);
                mma16816(acc[2 * f2 + 1], ah, bh[2], bh[3]);
                mma16816(acc[2 * f2],     ah, bl[0], bl[1]);
                mma16816(acc[2 * f2 + 1], ah, bl[2], bl[3]);
                mma16816(acc[2 * f2],     al, bh[0], bh[1]);
                mma16816(acc[2 * f2 + 1], al, bh[2], bh[3]);
            }
        }
        __syncthreads();
    }

    const int g = lane >> 2, tig = lane & 3;
    const size_t r0 = (size_t)(e0 + w * 16 + g) * OUTC;
    const size_t r1 = r0 + 8 * OUTC;
    #pragma unroll
    for (int f = 0; f < 12; f++) {
        int col = nb + f * 8 + tig * 2;
        float2 b2 = *(const float2*)&denseb[col];
        *(float2*)&out[r0 + col] = make_float2(acc[f][0] + b2.x, acc[f][1] + b2.y);
        *(float2*)&out[r1 + col] = make_float2(acc[f][2] + b2.x, acc[f][3] + b2.y);
    }
}

// ---------------------------------------------------------------------------
extern "C" void kernel_launch(void* const* d_in, const int* in_sizes, int n_in,
                              void* d_out, int out_size)
{
    const float* s_j    = (const float*)d_in[0];
    const float* dist   = (const float*)d_in[1];
    const int*   nbrs   = (const int*)  d_in[2];
    const float* ln_g   = (const float*)d_in[3];
    const float* ln_b   = (const float*)d_in[4];
    const float* Wq     = (const float*)d_in[5];
    const float* bq     = (const float*)d_in[6];
    const float* Wk     = (const float*)d_in[7];
    const float* bk     = (const float*)d_in[8];
    const float* Wv     = (const float*)d_in[9];
    const float* bv     = (const float*)d_in[10];
    const float* dkW    = (const float*)d_in[11];
    const float* dkb    = (const float*)d_in[12];
    const float* dvW    = (const float*)d_in[13];
    const float* dvb    = (const float*)d_in[14];
    const float* denseW = (const float*)d_in[15];
    const float* denseb = (const float*)d_in[16];
    float* out = (float*)d_out;

    int n_nodes = in_sizes[0] / F;    // 20000

    static cudaStream_t s2 = nullptr;
    static cudaEvent_t evm[5], evj;
    if (!s2) {
        cudaStreamCreateWithFlags(&s2, cudaStreamNonBlocking);
        for (int i = 0; i < 5; i++)
            cudaEventCreateWithFlags(&evm[i], cudaEventDisableTiming);
        cudaEventCreateWithFlags(&evj, cudaEventDisableTiming);
    }

    cudaFuncSetAttribute(qkv_mma_kernel, cudaFuncAttributeMaxDynamicSharedMemorySize, SMEM_QKV);
    cudaFuncSetAttribute(msg_kernel,     cudaFuncAttributeMaxDynamicSharedMemorySize, SMEM_MSG);
    cudaFuncSetAttribute(gemm_kernel,    cudaFuncAttributeMaxDynamicSharedMemorySize, SMEM_GEMM);

    dim3 gq((n_nodes + 127) / 128, 4, 4);
    qkv_mma_kernel<<<gq, 512, SMEM_QKV>>>(s_j, ln_g, ln_b, Wq, bq, Wk, bk, Wv, bv,
                                          denseW, n_nodes);

    for (int c = 0; c < 5; c++) {
        msg_kernel<<<ECHUNK / 64, 512, SMEM_MSG>>>(
            dist, nbrs, dkW, dkb, dvW, dvb, c * ECHUNK);
        cudaEventRecord(evm[c], 0);
        cudaStreamWaitEvent(s2, evm[c], 0);
        dim3 gg(4, ECHUNK / 128);
        gemm_kernel<<<gg, 256, SMEM_GEMM, s2>>>(denseb, out, c * ECHUNK);
    }
    cudaEventRecord(evj, s2);
    cudaStreamWaitEvent((cudaStream_t)0, evj, 0);
}